// round 1
// baseline (speedup 1.0000x reference)
#include <cuda_runtime.h>
#include <cuda_bf16.h>
#include <cstddef>

// Problem constants (fixed-shape problem)
#define N0c 200000
#define N1c 100000
#define N2c 50000
#define E1c 1600000
#define E2c 800000
#define FIN 128
#define FHID 256
#define FOUT 128

// deg layout: [0,N0) out1 | [N0, N0+N1) in1 | [+N1) out2 | [+N2) in2
#define OFF_OUT1 0
#define OFF_IN1  200000
#define OFF_OUT2 300000
#define OFF_IN2  400000
#define DEG_TOT  450000

// Scratch (no allocations allowed)
__device__ float g_deg[DEG_TOT];
__device__ float g_agg1[(size_t)N1c * FIN];   // 51.2 MB
__device__ float g_h[(size_t)N1c * FHID];     // 102.4 MB
__device__ float g_y[(size_t)N1c * FOUT];     // 51.2 MB

// ---------------------------------------------------------------------------
__global__ void zero_kernel(float4* __restrict__ p, int n4) {
    int i = blockIdx.x * blockDim.x + threadIdx.x;
    if (i < n4) p[i] = make_float4(0.f, 0.f, 0.f, 0.f);
}

__global__ void degree_kernel(const int* __restrict__ s1, const int* __restrict__ d1,
                              const int* __restrict__ s2, const int* __restrict__ d2) {
    int i = blockIdx.x * blockDim.x + threadIdx.x;
    if (i < E1c) {
        atomicAdd(&g_deg[OFF_OUT1 + s1[i]], 1.f);
        atomicAdd(&g_deg[OFF_IN1 + d1[i]], 1.f);
    }
    if (i < E2c) {
        atomicAdd(&g_deg[OFF_OUT2 + s2[i]], 1.f);
        atomicAdd(&g_deg[OFF_IN2 + d2[i]], 1.f);
    }
}

__global__ void rsqrt_kernel() {
    int i = blockIdx.x * blockDim.x + threadIdx.x;
    if (i < DEG_TOT) g_deg[i] = rsqrtf(fmaxf(g_deg[i], 1.f));
}

// ---------------------------------------------------------------------------
__device__ __forceinline__ void red_add_v4(float* a, float4 v) {
    asm volatile("red.global.add.v4.f32 [%0], {%1, %2, %3, %4};"
                 :: "l"(a), "f"(v.x), "f"(v.y), "f"(v.z), "f"(v.w) : "memory");
}

// One warp per edge; each lane handles one float4 of the 128-float feature row.
__global__ void scatter_kernel(const float* __restrict__ X,
                               const int* __restrict__ src,
                               const int* __restrict__ dst,
                               const float* __restrict__ sscale,
                               float* __restrict__ OUT, int E) {
    int t = blockIdx.x * blockDim.x + threadIdx.x;
    int e = t >> 5;
    if (e >= E) return;
    int lane = t & 31;
    int s = src[e], d = dst[e];
    float4 v = ((const float4*)X)[(size_t)s * 32 + lane];
    if (sscale) {
        float sc = sscale[s];
        v.x *= sc; v.y *= sc; v.z *= sc; v.w *= sc;
    }
    red_add_v4((float*)&((float4*)OUT)[(size_t)d * 32 + lane], v);
}

// ---------------------------------------------------------------------------
// C[m,n] = act( rowscale[m] * sum_k A[m,k]*B[k,n] + bias[n] )
// BM=128, BN=128, BK=8, 256 threads, 8x8 per-thread microtile.
__global__ __launch_bounds__(256) void sgemm_fused(
    const float* __restrict__ A, const float* __restrict__ B, float* __restrict__ C,
    int M, int N, int K,
    const float* __restrict__ rowscale, const float* __restrict__ bias, int do_relu)
{
    const int BM = 128, BN = 128, BK = 8, TM = 8, TN = 8;
    __shared__ float As[BK][BM];
    __shared__ float Bs[BK][BN];

    int tid = threadIdx.x;
    int bn = blockIdx.x, bm = blockIdx.y;
    int rowBase = bm * BM;
    int colBase = bn * BN;

    // A tile load: 128 rows x 8 cols = 1024 floats, 1 float4/thread
    int aRow = tid >> 1;
    int aCol = (tid & 1) * 4;
    // B tile load: 8 rows x 128 cols, 1 float4/thread
    int bRow = tid >> 5;
    int bCol = (tid & 31) * 4;

    int tr = tid >> 4;   // 0..15
    int tc = tid & 15;   // 0..15

    float acc[TM][TN];
#pragma unroll
    for (int i = 0; i < TM; i++)
#pragma unroll
        for (int j = 0; j < TN; j++) acc[i][j] = 0.f;

    for (int k0 = 0; k0 < K; k0 += BK) {
        float4 av = make_float4(0.f, 0.f, 0.f, 0.f);
        int gr = rowBase + aRow;
        if (gr < M) av = *(const float4*)&A[(size_t)gr * K + k0 + aCol];
        As[aCol + 0][aRow] = av.x;
        As[aCol + 1][aRow] = av.y;
        As[aCol + 2][aRow] = av.z;
        As[aCol + 3][aRow] = av.w;

        float4 bv = *(const float4*)&B[(size_t)(k0 + bRow) * N + colBase + bCol];
        *(float4*)&Bs[bRow][bCol] = bv;

        __syncthreads();
#pragma unroll
        for (int k = 0; k < BK; k++) {
            float ra[TM], rb[TN];
#pragma unroll
            for (int i = 0; i < TM; i++) ra[i] = As[k][tr * TM + i];
#pragma unroll
            for (int j = 0; j < TN; j++) rb[j] = Bs[k][tc * TN + j];
#pragma unroll
            for (int i = 0; i < TM; i++)
#pragma unroll
                for (int j = 0; j < TN; j++)
                    acc[i][j] = fmaf(ra[i], rb[j], acc[i][j]);
        }
        __syncthreads();
    }

    int col = colBase + tc * TN;
    float bvals[TN];
#pragma unroll
    for (int j = 0; j < TN; j++) bvals[j] = bias ? bias[col + j] : 0.f;

#pragma unroll
    for (int i = 0; i < TM; i++) {
        int m = rowBase + tr * TM + i;
        if (m >= M) continue;
        float s = rowscale ? rowscale[m] : 1.f;
        float out[TN];
#pragma unroll
        for (int j = 0; j < TN; j++) {
            float v = acc[i][j] * s + bvals[j];
            out[j] = do_relu ? fmaxf(v, 0.f) : v;
        }
        *(float4*)&C[(size_t)m * N + col]     = make_float4(out[0], out[1], out[2], out[3]);
        *(float4*)&C[(size_t)m * N + col + 4] = make_float4(out[4], out[5], out[6], out[7]);
    }
}

// ---------------------------------------------------------------------------
// out[m,:] = relu(out[m,:] * indeg2inv[m] + b2)
__global__ void finalize_kernel(float* __restrict__ out, const float* __restrict__ bias) {
    int t = blockIdx.x * blockDim.x + threadIdx.x;
    if (t >= N2c * (FOUT / 4)) return;
    int m = t >> 5;
    int c = t & 31;
    float s = g_deg[OFF_IN2 + m];
    float4 v = ((float4*)out)[t];
    float4 b = ((const float4*)bias)[c];
    v.x = fmaxf(fmaf(v.x, s, b.x), 0.f);
    v.y = fmaxf(fmaf(v.y, s, b.y), 0.f);
    v.z = fmaxf(fmaf(v.z, s, b.z), 0.f);
    v.w = fmaxf(fmaf(v.w, s, b.w), 0.f);
    ((float4*)out)[t] = v;
}

// ---------------------------------------------------------------------------
extern "C" void kernel_launch(void* const* d_in, const int* in_sizes, int n_in,
                              void* d_out, int out_size) {
    const float* x   = (const float*)d_in[0];
    const float* W1  = (const float*)d_in[1];
    const float* b1  = (const float*)d_in[2];
    const float* W2  = (const float*)d_in[3];
    const float* b2  = (const float*)d_in[4];
    const int* src1  = (const int*)d_in[5];
    const int* dst1  = (const int*)d_in[6];
    const int* src2  = (const int*)d_in[7];
    const int* dst2  = (const int*)d_in[8];
    float* out = (float*)d_out;

    float *deg, *agg1, *h, *y;
    cudaGetSymbolAddress((void**)&deg, g_deg);
    cudaGetSymbolAddress((void**)&agg1, g_agg1);
    cudaGetSymbolAddress((void**)&h, g_h);
    cudaGetSymbolAddress((void**)&y, g_y);

    const int TB = 256;

    // Zero: degrees, agg1, and d_out (poisoned by harness)
    {
        int n4 = DEG_TOT / 4;
        zero_kernel<<<(n4 + TB - 1) / TB, TB>>>((float4*)deg, n4);
        n4 = (int)((size_t)N1c * FIN / 4);
        zero_kernel<<<(n4 + TB - 1) / TB, TB>>>((float4*)agg1, n4);
        n4 = (int)((size_t)N2c * FOUT / 4);
        zero_kernel<<<(n4 + TB - 1) / TB, TB>>>((float4*)out, n4);
    }

    // Degrees + rsqrt
    degree_kernel<<<(E1c + TB - 1) / TB, TB>>>(src1, dst1, src2, dst2);
    rsqrt_kernel<<<(DEG_TOT + TB - 1) / TB, TB>>>();

    // Layer 1: agg1 = segsum(x * outdeg1^-1/2 [src1]) over dst1
    {
        long long threads = (long long)E1c * 32;
        scatter_kernel<<<(unsigned)((threads + TB - 1) / TB), TB>>>(
            x, src1, dst1, deg + OFF_OUT1, agg1, E1c);
    }
    // h = relu( indeg1inv[m] * agg1 @ W1 + b1 )
    {
        dim3 grid(FHID / 128, (N1c + 127) / 128);
        sgemm_fused<<<grid, 256>>>(agg1, W1, h, N1c, FHID, FIN, deg + OFF_IN1, b1, 1);
    }
    // y = outdeg2inv[m] * h @ W2   (aggregate after GEMM: agg(h)@W2 == agg(h@W2))
    {
        dim3 grid(FOUT / 128, (N1c + 127) / 128);
        sgemm_fused<<<grid, 256>>>(h, W2, y, N1c, FOUT, FHID, deg + OFF_OUT2, nullptr, 0);
    }
    // Layer 2 scatter: out += y[src2] over dst2
    {
        long long threads = (long long)E2c * 32;
        scatter_kernel<<<(unsigned)((threads + TB - 1) / TB), TB>>>(
            y, src2, dst2, nullptr, out, E2c);
    }
    // out = relu(out * indeg2inv + b2)
    {
        int threads = N2c * (FOUT / 4);
        finalize_kernel<<<(threads + TB - 1) / TB, TB>>>(out, b2);
    }
}

// round 2
// speedup vs baseline: 1.3423x; 1.3423x over previous
#include <cuda_runtime.h>
#include <cuda_bf16.h>
#include <cstdint>
#include <cstddef>

// Problem constants (fixed-shape problem)
#define N0c 200000
#define N1c 100000
#define N2c 50000
#define E1c 1600000
#define E2c 800000
#define FIN 128
#define FHID 256
#define FOUT 128

// deg layout: [0,N0) out1 | [N0, N0+N1) in1 | [+N1) out2 | [+N2) in2
#define OFF_OUT1 0
#define OFF_IN1  200000
#define OFF_OUT2 300000
#define OFF_IN2  400000
#define DEG_TOT  450000

// Scratch (no allocations allowed)
__device__ float g_deg[DEG_TOT];
__device__ float g_agg1[(size_t)N1c * FIN];   // 51.2 MB
__device__ float g_h[(size_t)N1c * FHID];     // 102.4 MB
__device__ float g_y[(size_t)N1c * FOUT];     // 51.2 MB

// ---------------------------------------------------------------------------
__global__ void zero_kernel(float4* __restrict__ p, int n4) {
    int i = blockIdx.x * blockDim.x + threadIdx.x;
    if (i < n4) p[i] = make_float4(0.f, 0.f, 0.f, 0.f);
}

__global__ void degree_kernel(const int* __restrict__ s1, const int* __restrict__ d1,
                              const int* __restrict__ s2, const int* __restrict__ d2) {
    int i = blockIdx.x * blockDim.x + threadIdx.x;
    if (i < E1c) {
        atomicAdd(&g_deg[OFF_OUT1 + s1[i]], 1.f);
        atomicAdd(&g_deg[OFF_IN1 + d1[i]], 1.f);
    }
    if (i < E2c) {
        atomicAdd(&g_deg[OFF_OUT2 + s2[i]], 1.f);
        atomicAdd(&g_deg[OFF_IN2 + d2[i]], 1.f);
    }
}

__global__ void rsqrt_kernel() {
    int i = blockIdx.x * blockDim.x + threadIdx.x;
    if (i < DEG_TOT) g_deg[i] = rsqrtf(fmaxf(g_deg[i], 1.f));
}

// ---------------------------------------------------------------------------
__device__ __forceinline__ void red_add_v4(float* a, float4 v) {
    asm volatile("red.global.add.v4.f32 [%0], {%1, %2, %3, %4};"
                 :: "l"(a), "f"(v.x), "f"(v.y), "f"(v.z), "f"(v.w) : "memory");
}

// One warp per edge; each lane handles one float4 of the 128-float feature row.
__global__ void scatter_kernel(const float* __restrict__ X,
                               const int* __restrict__ src,
                               const int* __restrict__ dst,
                               const float* __restrict__ sscale,
                               float* __restrict__ OUT, int E) {
    int t = blockIdx.x * blockDim.x + threadIdx.x;
    int e = t >> 5;
    if (e >= E) return;
    int lane = t & 31;
    int s = src[e], d = dst[e];
    float4 v = ((const float4*)X)[(size_t)s * 32 + lane];
    if (sscale) {
        float sc = sscale[s];
        v.x *= sc; v.y *= sc; v.z *= sc; v.w *= sc;
    }
    red_add_v4((float*)&((float4*)OUT)[(size_t)d * 32 + lane], v);
}

// ---------------------------------------------------------------------------
// TF32 tensor-core GEMM: C[m,n] = act( rowscale[m]*sum_k A[m,k]B[k,n] + bias[n] )
// BM=128, BN=128, BK=32, 256 threads (8 warps as 4(M) x 2(N)), warp tile 32x64,
// mma.sync.aligned.m16n8k8.tf32. Conflict-free padded smem fragment loads.
// ---------------------------------------------------------------------------
#define ASTRIDE 36
#define BSTRIDE 132

__device__ __forceinline__ uint32_t f2tf32(float f) {
    uint32_t r;
    asm("cvt.rna.tf32.f32 %0, %1;" : "=r"(r) : "f"(f));
    return r;
}

__device__ __forceinline__ void mma_tf32(float c[4], const uint32_t a[4], const uint32_t b[2]) {
    asm volatile(
        "mma.sync.aligned.m16n8k8.row.col.f32.tf32.tf32.f32 "
        "{%0,%1,%2,%3}, {%4,%5,%6,%7}, {%8,%9}, {%0,%1,%2,%3};"
        : "+f"(c[0]), "+f"(c[1]), "+f"(c[2]), "+f"(c[3])
        : "r"(a[0]), "r"(a[1]), "r"(a[2]), "r"(a[3]), "r"(b[0]), "r"(b[1]));
}

__global__ __launch_bounds__(256) void gemm_tf32_fused(
    const float* __restrict__ A, const float* __restrict__ B, float* __restrict__ C,
    int M, int N, int K,
    const float* __restrict__ rowscale, const float* __restrict__ bias, int do_relu)
{
    const int BM = 128, BN = 128, BK = 32;
    __shared__ uint32_t As[BM][ASTRIDE];   // [m][k], pad 36: frag loads conflict-free
    __shared__ uint32_t Bs[BK][BSTRIDE];   // [k][n], pad 132

    int tid = threadIdx.x;
    int wid = tid >> 5, lane = tid & 31;
    int g = lane >> 2, tig = lane & 3;
    int warp_m = (wid & 3) * 32;
    int warp_n = (wid >> 2) * 64;
    int rowBase = blockIdx.y * BM;
    int colBase = blockIdx.x * BN;

    float c[2][8][4];
#pragma unroll
    for (int mi = 0; mi < 2; mi++)
#pragma unroll
        for (int ni = 0; ni < 8; ni++)
#pragma unroll
            for (int q = 0; q < 4; q++) c[mi][ni][q] = 0.f;

    float4 ra[4], rb[4];

    // Prefetch tile 0
#pragma unroll
    for (int i = 0; i < 4; i++) {
        int f4 = tid + 256 * i;
        int arow = f4 >> 3, acolv = f4 & 7;          // A tile 128x32
        int gr = rowBase + arow;
        ra[i] = (gr < M) ? *(const float4*)&A[(size_t)gr * K + acolv * 4]
                         : make_float4(0.f, 0.f, 0.f, 0.f);
        int brow = f4 >> 5, bcolv = f4 & 31;         // B tile 32x128
        rb[i] = *(const float4*)&B[(size_t)brow * N + colBase + bcolv * 4];
    }

    for (int k0 = 0; k0 < K; k0 += BK) {
        // Stage regs -> smem (tf32-converted)
#pragma unroll
        for (int i = 0; i < 4; i++) {
            int f4 = tid + 256 * i;
            int arow = f4 >> 3, acol = (f4 & 7) * 4;
            As[arow][acol + 0] = f2tf32(ra[i].x);
            As[arow][acol + 1] = f2tf32(ra[i].y);
            As[arow][acol + 2] = f2tf32(ra[i].z);
            As[arow][acol + 3] = f2tf32(ra[i].w);
            int brow = f4 >> 5, bcol = (f4 & 31) * 4;
            Bs[brow][bcol + 0] = f2tf32(rb[i].x);
            Bs[brow][bcol + 1] = f2tf32(rb[i].y);
            Bs[brow][bcol + 2] = f2tf32(rb[i].z);
            Bs[brow][bcol + 3] = f2tf32(rb[i].w);
        }
        __syncthreads();

        // Prefetch next tile while computing this one
        int k1 = k0 + BK;
        if (k1 < K) {
#pragma unroll
            for (int i = 0; i < 4; i++) {
                int f4 = tid + 256 * i;
                int arow = f4 >> 3, acolv = f4 & 7;
                int gr = rowBase + arow;
                ra[i] = (gr < M) ? *(const float4*)&A[(size_t)gr * K + k1 + acolv * 4]
                                 : make_float4(0.f, 0.f, 0.f, 0.f);
                int brow = f4 >> 5, bcolv = f4 & 31;
                rb[i] = *(const float4*)&B[(size_t)(k1 + brow) * N + colBase + bcolv * 4];
            }
        }

#pragma unroll
        for (int kk = 0; kk < BK; kk += 8) {
            uint32_t af[2][4], bf[8][2];
#pragma unroll
            for (int mi = 0; mi < 2; mi++) {
                int m = warp_m + mi * 16 + g;
                af[mi][0] = As[m][kk + tig];
                af[mi][1] = As[m + 8][kk + tig];
                af[mi][2] = As[m][kk + tig + 4];
                af[mi][3] = As[m + 8][kk + tig + 4];
            }
#pragma unroll
            for (int ni = 0; ni < 8; ni++) {
                int n = warp_n + ni * 8 + g;
                bf[ni][0] = Bs[kk + tig][n];
                bf[ni][1] = Bs[kk + tig + 4][n];
            }
#pragma unroll
            for (int mi = 0; mi < 2; mi++)
#pragma unroll
                for (int ni = 0; ni < 8; ni++)
                    mma_tf32(c[mi][ni], af[mi], bf[ni]);
        }
        __syncthreads();
    }

    // Epilogue: rowscale * acc + bias, optional relu
#pragma unroll
    for (int mi = 0; mi < 2; mi++) {
#pragma unroll
        for (int half = 0; half < 2; half++) {
            int row = rowBase + warp_m + mi * 16 + g + half * 8;
            if (row >= M) continue;
            float s = rowscale ? rowscale[row] : 1.f;
#pragma unroll
            for (int ni = 0; ni < 8; ni++) {
                int col = colBase + warp_n + ni * 8 + 2 * tig;
                float v0 = c[mi][ni][half * 2 + 0] * s;
                float v1 = c[mi][ni][half * 2 + 1] * s;
                if (bias) { v0 += bias[col]; v1 += bias[col + 1]; }
                if (do_relu) { v0 = fmaxf(v0, 0.f); v1 = fmaxf(v1, 0.f); }
                *(float2*)&C[(size_t)row * N + col] = make_float2(v0, v1);
            }
        }
    }
}

// ---------------------------------------------------------------------------
// out[m,:] = relu(out[m,:] * indeg2inv[m] + b2)
__global__ void finalize_kernel(float* __restrict__ out, const float* __restrict__ bias) {
    int t = blockIdx.x * blockDim.x + threadIdx.x;
    if (t >= N2c * (FOUT / 4)) return;
    int m = t >> 5;
    int cidx = t & 31;
    float s = g_deg[OFF_IN2 + m];
    float4 v = ((float4*)out)[t];
    float4 b = ((const float4*)bias)[cidx];
    v.x = fmaxf(fmaf(v.x, s, b.x), 0.f);
    v.y = fmaxf(fmaf(v.y, s, b.y), 0.f);
    v.z = fmaxf(fmaf(v.z, s, b.z), 0.f);
    v.w = fmaxf(fmaf(v.w, s, b.w), 0.f);
    ((float4*)out)[t] = v;
}

// ---------------------------------------------------------------------------
extern "C" void kernel_launch(void* const* d_in, const int* in_sizes, int n_in,
                              void* d_out, int out_size) {
    const float* x   = (const float*)d_in[0];
    const float* W1  = (const float*)d_in[1];
    const float* b1  = (const float*)d_in[2];
    const float* W2  = (const float*)d_in[3];
    const float* b2  = (const float*)d_in[4];
    const int* src1  = (const int*)d_in[5];
    const int* dst1  = (const int*)d_in[6];
    const int* src2  = (const int*)d_in[7];
    const int* dst2  = (const int*)d_in[8];
    float* out = (float*)d_out;

    float *deg, *agg1, *h, *y;
    cudaGetSymbolAddress((void**)&deg, g_deg);
    cudaGetSymbolAddress((void**)&agg1, g_agg1);
    cudaGetSymbolAddress((void**)&h, g_h);
    cudaGetSymbolAddress((void**)&y, g_y);

    const int TB = 256;

    // Zero: degrees, agg1, and d_out (poisoned by harness)
    {
        int n4 = DEG_TOT / 4;
        zero_kernel<<<(n4 + TB - 1) / TB, TB>>>((float4*)deg, n4);
        n4 = (int)((size_t)N1c * FIN / 4);
        zero_kernel<<<(n4 + TB - 1) / TB, TB>>>((float4*)agg1, n4);
        n4 = (int)((size_t)N2c * FOUT / 4);
        zero_kernel<<<(n4 + TB - 1) / TB, TB>>>((float4*)out, n4);
    }

    // Degrees + rsqrt
    degree_kernel<<<(E1c + TB - 1) / TB, TB>>>(src1, dst1, src2, dst2);
    rsqrt_kernel<<<(DEG_TOT + TB - 1) / TB, TB>>>();

    // Layer 1: agg1 = segsum(x * outdeg1^-1/2 [src1]) over dst1
    {
        long long threads = (long long)E1c * 32;
        scatter_kernel<<<(unsigned)((threads + TB - 1) / TB), TB>>>(
            x, src1, dst1, deg + OFF_OUT1, agg1, E1c);
    }
    // h = relu( indeg1inv[m] * agg1 @ W1 + b1 )
    {
        dim3 grid(FHID / 128, (N1c + 127) / 128);
        gemm_tf32_fused<<<grid, 256>>>(agg1, W1, h, N1c, FHID, FIN, deg + OFF_IN1, b1, 1);
    }
    // y = outdeg2inv[m] * h @ W2   (aggregate after GEMM: agg(h)@W2 == agg(h@W2))
    {
        dim3 grid(FOUT / 128, (N1c + 127) / 128);
        gemm_tf32_fused<<<grid, 256>>>(h, W2, y, N1c, FOUT, FHID, deg + OFF_OUT2, nullptr, 0);
    }
    // Layer 2 scatter: out += y[src2] over dst2
    {
        long long threads = (long long)E2c * 32;
        scatter_kernel<<<(unsigned)((threads + TB - 1) / TB), TB>>>(
            y, src2, dst2, nullptr, out, E2c);
    }
    // out = relu(out * indeg2inv + b2)
    {
        int threads = N2c * (FOUT / 4);
        finalize_kernel<<<(threads + TB - 1) / TB, TB>>>(out, b2);
    }
}

// round 3
// speedup vs baseline: 1.9126x; 1.4249x over previous
#include <cuda_runtime.h>
#include <cuda_bf16.h>
#include <cstdint>
#include <cstddef>

// Problem constants (fixed-shape problem)
#define N0c 200000
#define N1c 100000
#define N2c 50000
#define E1c 1600000
#define E2c 800000
#define FIN 128
#define FHID 256
#define FOUT 128

// degree/count layout: [0,N0) out1 | [N0,+N1) in1 | [+N1) out2 | [+N2) in2
#define OFF_OUT1 0
#define OFF_IN1  200000
#define OFF_OUT2 300000
#define OFF_IN2  400000
#define DEG_TOT  450000

#define NB1 ((N1c + 255) / 256)   // 391
#define NB2 ((N2c + 255) / 256)   // 196
#define NBT (NB1 + NB2)           // 587

// Scratch (no allocations allowed)
__device__ int   g_icnt[DEG_TOT];
__device__ float g_deg[DEG_TOT];
__device__ int   g_off1[N1c + 1];
__device__ int   g_cur1[N1c];
__device__ int   g_off2[N2c + 1];
__device__ int   g_cur2[N2c];
__device__ int   g_csr1[E1c];
__device__ int   g_csr2[E2c];
__device__ int   g_bsum[1024];
__device__ int   g_boff[1024];
__device__ float g_agg1[(size_t)N1c * FIN];   // 51.2 MB
__device__ float g_h[(size_t)N1c * FHID];     // 102.4 MB
__device__ float g_y[(size_t)N1c * FOUT];     // 51.2 MB

// ---------------------------------------------------------------------------
__global__ void zero_icnt_kernel() {
    int i = blockIdx.x * blockDim.x + threadIdx.x;
    if (i < DEG_TOT / 4) ((int4*)g_icnt)[i] = make_int4(0, 0, 0, 0);
}

__global__ void degree_kernel(const int* __restrict__ s1, const int* __restrict__ d1,
                              const int* __restrict__ s2, const int* __restrict__ d2) {
    int i = blockIdx.x * blockDim.x + threadIdx.x;
    if (i < E1c) {
        atomicAdd(&g_icnt[OFF_OUT1 + s1[i]], 1);
        atomicAdd(&g_icnt[OFF_IN1 + d1[i]], 1);
    }
    if (i < E2c) {
        atomicAdd(&g_icnt[OFF_OUT2 + s2[i]], 1);
        atomicAdd(&g_icnt[OFF_IN2 + d2[i]], 1);
    }
}

__global__ void convert_deg_kernel() {
    int i = blockIdx.x * blockDim.x + threadIdx.x;
    if (i < DEG_TOT) g_deg[i] = rsqrtf((float)max(g_icnt[i], 1));
}

// --- 3-pass exclusive scan of in-degree counts -> CSR offsets ---------------
__global__ __launch_bounds__(256) void scan_pass1() {
    __shared__ int sh[256];
    int b = blockIdx.x, tid = threadIdx.x;
    int v = 0;
    if (b < NB1) {
        int idx = b * 256 + tid;
        if (idx < N1c) v = g_icnt[OFF_IN1 + idx];
    } else {
        int idx = (b - NB1) * 256 + tid;
        if (idx < N2c) v = g_icnt[OFF_IN2 + idx];
    }
    sh[tid] = v;
    __syncthreads();
    for (int s = 128; s > 0; s >>= 1) {
        if (tid < s) sh[tid] += sh[tid + s];
        __syncthreads();
    }
    if (tid == 0) g_bsum[b] = sh[0];
}

__global__ __launch_bounds__(512) void scan_pass2() {
    __shared__ int sh[512];
    int tid = threadIdx.x;
    // segment 1: blocks [0, NB1)
    int v = (tid < NB1) ? g_bsum[tid] : 0;
    sh[tid] = v;
    __syncthreads();
    for (int s = 1; s < 512; s <<= 1) {
        int a = (tid >= s) ? sh[tid - s] : 0;
        __syncthreads();
        sh[tid] += a;
        __syncthreads();
    }
    if (tid < NB1) g_boff[tid] = sh[tid] - v;
    __syncthreads();
    // segment 2: blocks [NB1, NBT)
    int v2 = (tid < NB2) ? g_bsum[NB1 + tid] : 0;
    sh[tid] = v2;
    __syncthreads();
    for (int s = 1; s < 512; s <<= 1) {
        int a = (tid >= s) ? sh[tid - s] : 0;
        __syncthreads();
        sh[tid] += a;
        __syncthreads();
    }
    if (tid < NB2) g_boff[NB1 + tid] = sh[tid] - v2;
}

__global__ __launch_bounds__(256) void scan_pass3() {
    __shared__ int sh[256];
    int b = blockIdx.x, tid = threadIdx.x;
    int v = 0, idx = 0;
    bool g1 = (b < NB1);
    if (g1) {
        idx = b * 256 + tid;
        if (idx < N1c) v = g_icnt[OFF_IN1 + idx];
    } else {
        idx = (b - NB1) * 256 + tid;
        if (idx < N2c) v = g_icnt[OFF_IN2 + idx];
    }
    sh[tid] = v;
    __syncthreads();
    for (int s = 1; s < 256; s <<= 1) {
        int a = (tid >= s) ? sh[tid - s] : 0;
        __syncthreads();
        sh[tid] += a;
        __syncthreads();
    }
    int excl = sh[tid] - v + g_boff[b];
    if (g1) {
        if (idx < N1c) { g_off1[idx] = excl; g_cur1[idx] = excl; }
    } else {
        if (idx < N2c) { g_off2[idx] = excl; g_cur2[idx] = excl; }
    }
    if (b == 0 && tid == 0) { g_off1[N1c] = E1c; g_off2[N2c] = E2c; }
}

// --- CSR fill (counting-sort edges by dst) ----------------------------------
__global__ void fill_kernel(const int* __restrict__ s1, const int* __restrict__ d1,
                            const int* __restrict__ s2, const int* __restrict__ d2) {
    int i = blockIdx.x * blockDim.x + threadIdx.x;
    if (i < E1c) {
        int p = atomicAdd(&g_cur1[d1[i]], 1);
        g_csr1[p] = s1[i];
    }
    if (i < E2c) {
        int p = atomicAdd(&g_cur2[d2[i]], 1);
        g_csr2[p] = s2[i];
    }
}

// --- Gather-aggregate layer 1: agg1[d] = sum_e x[src_e] * outdeg1inv[src_e] -
__global__ __launch_bounds__(256) void agg1_kernel(const float* __restrict__ X) {
    int w = (blockIdx.x * blockDim.x + threadIdx.x) >> 5;
    if (w >= N1c) return;
    int lane = threadIdx.x & 31;
    int i = g_off1[w], end = g_off1[w + 1];
    float4 acc = make_float4(0.f, 0.f, 0.f, 0.f);
    const float4* X4 = (const float4*)X;
    for (; i + 1 < end; i += 2) {
        int s0 = g_csr1[i], s1 = g_csr1[i + 1];
        float c0 = g_deg[OFF_OUT1 + s0], c1 = g_deg[OFF_OUT1 + s1];
        float4 v0 = X4[(size_t)s0 * 32 + lane];
        float4 v1 = X4[(size_t)s1 * 32 + lane];
        acc.x += v0.x * c0 + v1.x * c1;
        acc.y += v0.y * c0 + v1.y * c1;
        acc.z += v0.z * c0 + v1.z * c1;
        acc.w += v0.w * c0 + v1.w * c1;
    }
    if (i < end) {
        int s0 = g_csr1[i];
        float c0 = g_deg[OFF_OUT1 + s0];
        float4 v0 = X4[(size_t)s0 * 32 + lane];
        acc.x += v0.x * c0; acc.y += v0.y * c0;
        acc.z += v0.z * c0; acc.w += v0.w * c0;
    }
    ((float4*)g_agg1)[(size_t)w * 32 + lane] = acc;
}

// --- Gather-aggregate layer 2 + fused epilogue ------------------------------
// out[d] = relu( indeg2inv[d] * sum_e y[src_e] + b2 )   (y already has outdeg2inv)
__global__ __launch_bounds__(256) void agg2_kernel(const float* __restrict__ Y,
                                                   const float* __restrict__ bias,
                                                   float* __restrict__ OUT) {
    int w = (blockIdx.x * blockDim.x + threadIdx.x) >> 5;
    if (w >= N2c) return;
    int lane = threadIdx.x & 31;
    int i = g_off2[w], end = g_off2[w + 1];
    float4 acc = make_float4(0.f, 0.f, 0.f, 0.f);
    const float4* Y4 = (const float4*)Y;
    for (; i + 1 < end; i += 2) {
        int s0 = g_csr2[i], s1 = g_csr2[i + 1];
        float4 v0 = Y4[(size_t)s0 * 32 + lane];
        float4 v1 = Y4[(size_t)s1 * 32 + lane];
        acc.x += v0.x + v1.x; acc.y += v0.y + v1.y;
        acc.z += v0.z + v1.z; acc.w += v0.w + v1.w;
    }
    if (i < end) {
        int s0 = g_csr2[i];
        float4 v0 = Y4[(size_t)s0 * 32 + lane];
        acc.x += v0.x; acc.y += v0.y; acc.z += v0.z; acc.w += v0.w;
    }
    float s = g_deg[OFF_IN2 + w];
    float4 b = ((const float4*)bias)[lane];
    acc.x = fmaxf(fmaf(acc.x, s, b.x), 0.f);
    acc.y = fmaxf(fmaf(acc.y, s, b.y), 0.f);
    acc.z = fmaxf(fmaf(acc.z, s, b.z), 0.f);
    acc.w = fmaxf(fmaf(acc.w, s, b.w), 0.f);
    ((float4*)OUT)[(size_t)w * 32 + lane] = acc;
}

// ---------------------------------------------------------------------------
// TF32 tensor-core GEMM: C[m,n] = act( rowscale[m]*sum_k A[m,k]B[k,n] + bias[n] )
// BM=128, BN=128, BK=32, 256 threads (8 warps as 4(M) x 2(N)), warp tile 32x64.
// ---------------------------------------------------------------------------
#define ASTRIDE 36
#define BSTRIDE 132

__device__ __forceinline__ uint32_t f2tf32(float f) {
    uint32_t r;
    asm("cvt.rna.tf32.f32 %0, %1;" : "=r"(r) : "f"(f));
    return r;
}

__device__ __forceinline__ void mma_tf32(float c[4], const uint32_t a[4], const uint32_t b[2]) {
    asm volatile(
        "mma.sync.aligned.m16n8k8.row.col.f32.tf32.tf32.f32 "
        "{%0,%1,%2,%3}, {%4,%5,%6,%7}, {%8,%9}, {%0,%1,%2,%3};"
        : "+f"(c[0]), "+f"(c[1]), "+f"(c[2]), "+f"(c[3])
        : "r"(a[0]), "r"(a[1]), "r"(a[2]), "r"(a[3]), "r"(b[0]), "r"(b[1]));
}

__global__ __launch_bounds__(256) void gemm_tf32_fused(
    const float* __restrict__ A, const float* __restrict__ B, float* __restrict__ C,
    int M, int N, int K,
    const float* __restrict__ rowscale, const float* __restrict__ bias, int do_relu)
{
    const int BM = 128, BK = 32;
    __shared__ uint32_t As[BM][ASTRIDE];
    __shared__ uint32_t Bs[BK][BSTRIDE];

    int tid = threadIdx.x;
    int wid = tid >> 5, lane = tid & 31;
    int g = lane >> 2, tig = lane & 3;
    int warp_m = (wid & 3) * 32;
    int warp_n = (wid >> 2) * 64;
    int rowBase = blockIdx.y * BM;
    int colBase = blockIdx.x * 128;

    float c[2][8][4];
#pragma unroll
    for (int mi = 0; mi < 2; mi++)
#pragma unroll
        for (int ni = 0; ni < 8; ni++)
#pragma unroll
            for (int q = 0; q < 4; q++) c[mi][ni][q] = 0.f;

    float4 ra[4], rb[4];

#pragma unroll
    for (int i = 0; i < 4; i++) {
        int f4 = tid + 256 * i;
        int arow = f4 >> 3, acolv = f4 & 7;
        int gr = rowBase + arow;
        ra[i] = (gr < M) ? *(const float4*)&A[(size_t)gr * K + acolv * 4]
                         : make_float4(0.f, 0.f, 0.f, 0.f);
        int brow = f4 >> 5, bcolv = f4 & 31;
        rb[i] = *(const float4*)&B[(size_t)brow * N + colBase + bcolv * 4];
    }

    for (int k0 = 0; k0 < K; k0 += BK) {
#pragma unroll
        for (int i = 0; i < 4; i++) {
            int f4 = tid + 256 * i;
            int arow = f4 >> 3, acol = (f4 & 7) * 4;
            As[arow][acol + 0] = f2tf32(ra[i].x);
            As[arow][acol + 1] = f2tf32(ra[i].y);
            As[arow][acol + 2] = f2tf32(ra[i].z);
            As[arow][acol + 3] = f2tf32(ra[i].w);
            int brow = f4 >> 5, bcol = (f4 & 31) * 4;
            Bs[brow][bcol + 0] = f2tf32(rb[i].x);
            Bs[brow][bcol + 1] = f2tf32(rb[i].y);
            Bs[brow][bcol + 2] = f2tf32(rb[i].z);
            Bs[brow][bcol + 3] = f2tf32(rb[i].w);
        }
        __syncthreads();

        int k1 = k0 + BK;
        if (k1 < K) {
#pragma unroll
            for (int i = 0; i < 4; i++) {
                int f4 = tid + 256 * i;
                int arow = f4 >> 3, acolv = f4 & 7;
                int gr = rowBase + arow;
                ra[i] = (gr < M) ? *(const float4*)&A[(size_t)gr * K + k1 + acolv * 4]
                                 : make_float4(0.f, 0.f, 0.f, 0.f);
                int brow = f4 >> 5, bcolv = f4 & 31;
                rb[i] = *(const float4*)&B[(size_t)(k1 + brow) * N + colBase + bcolv * 4];
            }
        }

#pragma unroll
        for (int kk = 0; kk < BK; kk += 8) {
            uint32_t af[2][4], bf[8][2];
#pragma unroll
            for (int mi = 0; mi < 2; mi++) {
                int m = warp_m + mi * 16 + g;
                af[mi][0] = As[m][kk + tig];
                af[mi][1] = As[m + 8][kk + tig];
                af[mi][2] = As[m][kk + tig + 4];
                af[mi][3] = As[m + 8][kk + tig + 4];
            }
#pragma unroll
            for (int ni = 0; ni < 8; ni++) {
                int n = warp_n + ni * 8 + g;
                bf[ni][0] = Bs[kk + tig][n];
                bf[ni][1] = Bs[kk + tig + 4][n];
            }
#pragma unroll
            for (int mi = 0; mi < 2; mi++)
#pragma unroll
                for (int ni = 0; ni < 8; ni++)
                    mma_tf32(c[mi][ni], af[mi], bf[ni]);
        }
        __syncthreads();
    }

#pragma unroll
    for (int mi = 0; mi < 2; mi++) {
#pragma unroll
        for (int half = 0; half < 2; half++) {
            int row = rowBase + warp_m + mi * 16 + g + half * 8;
            if (row >= M) continue;
            float s = rowscale ? rowscale[row] : 1.f;
#pragma unroll
            for (int ni = 0; ni < 8; ni++) {
                int col = colBase + warp_n + ni * 8 + 2 * tig;
                float v0 = c[mi][ni][half * 2 + 0] * s;
                float v1 = c[mi][ni][half * 2 + 1] * s;
                if (bias) { v0 += bias[col]; v1 += bias[col + 1]; }
                if (do_relu) { v0 = fmaxf(v0, 0.f); v1 = fmaxf(v1, 0.f); }
                *(float2*)&C[(size_t)row * N + col] = make_float2(v0, v1);
            }
        }
    }
}

// ---------------------------------------------------------------------------
extern "C" void kernel_launch(void* const* d_in, const int* in_sizes, int n_in,
                              void* d_out, int out_size) {
    const float* x   = (const float*)d_in[0];
    const float* W1  = (const float*)d_in[1];
    const float* b1  = (const float*)d_in[2];
    const float* W2  = (const float*)d_in[3];
    const float* b2  = (const float*)d_in[4];
    const int* src1  = (const int*)d_in[5];
    const int* dst1  = (const int*)d_in[6];
    const int* src2  = (const int*)d_in[7];
    const int* dst2  = (const int*)d_in[8];
    float* out = (float*)d_out;

    float *deg, *agg1, *h, *y;
    cudaGetSymbolAddress((void**)&deg, g_deg);
    cudaGetSymbolAddress((void**)&agg1, g_agg1);
    cudaGetSymbolAddress((void**)&h, g_h);
    cudaGetSymbolAddress((void**)&y, g_y);

    const int TB = 256;

    // Degrees (int counts) + CSR build
    zero_icnt_kernel<<<(DEG_TOT / 4 + TB - 1) / TB, TB>>>();
    degree_kernel<<<(E1c + TB - 1) / TB, TB>>>(src1, dst1, src2, dst2);
    scan_pass1<<<NBT, 256>>>();
    scan_pass2<<<1, 512>>>();
    scan_pass3<<<NBT, 256>>>();
    convert_deg_kernel<<<(DEG_TOT + TB - 1) / TB, TB>>>();
    fill_kernel<<<(E1c + TB - 1) / TB, TB>>>(src1, dst1, src2, dst2);

    // Layer 1 aggregate (CSR gather): agg1 = segsum(x * outdeg1^-1/2)
    agg1_kernel<<<(N1c * 32 + TB - 1) / TB, TB>>>(x);

    // h = relu( indeg1inv[m] * agg1 @ W1 + b1 )
    {
        dim3 grid(FHID / 128, (N1c + 127) / 128);
        gemm_tf32_fused<<<grid, 256>>>(agg1, W1, h, N1c, FHID, FIN, deg + OFF_IN1, b1, 1);
    }
    // y = outdeg2inv[m] * (h @ W2)
    {
        dim3 grid(FOUT / 128, (N1c + 127) / 128);
        gemm_tf32_fused<<<grid, 256>>>(h, W2, y, N1c, FOUT, FHID, deg + OFF_OUT2, nullptr, 0);
    }
    // Layer 2 aggregate + fused scale/bias/relu -> out
    agg2_kernel<<<(N2c * 32 + TB - 1) / TB, TB>>>(y, b2, out);
}

// round 4
// speedup vs baseline: 2.2035x; 1.1521x over previous
#include <cuda_runtime.h>
#include <cuda_bf16.h>
#include <cstdint>
#include <cstddef>

// Problem constants (fixed-shape problem)
#define N0c 200000
#define N1c 100000
#define N2c 50000
#define E1c 1600000
#define E2c 800000
#define FIN 128
#define FHID 256
#define FOUT 128

// degree/count layout: [0,N0) out1 | [N0,+N1) in1 | [+N1) out2 | [+N2) in2
#define OFF_OUT1 0
#define OFF_IN1  200000
#define OFF_OUT2 300000
#define OFF_IN2  400000
#define DEG_TOT  450000

#define NB1 ((N1c + 255) / 256)   // 391
#define NB2 ((N2c + 255) / 256)   // 196
#define NBT (NB1 + NB2)           // 587

// Scratch (no allocations allowed)
__device__ int   g_icnt[DEG_TOT];
__device__ float g_deg[DEG_TOT];
__device__ int   g_off1[N1c + 1];
__device__ int   g_cur1[N1c];
__device__ int   g_off2[N2c + 1];
__device__ int   g_cur2[N2c];
__device__ int   g_csr1[E1c];
__device__ int   g_csr2[E2c];
__device__ int   g_bsum[1024];
__device__ int   g_boff[1024];
__device__ float g_wr1[FIN * FHID];           // tf32-rounded W1
__device__ float g_wr2[FHID * FOUT];          // tf32-rounded W2
__device__ float g_agg1[(size_t)N1c * FIN];   // 51.2 MB (tf32-rounded)
__device__ float g_h[(size_t)N1c * FHID];     // 102.4 MB (tf32-rounded)
__device__ float g_y[(size_t)N1c * FOUT];     // 51.2 MB

__device__ __forceinline__ uint32_t f2tf32(float f) {
    uint32_t r;
    asm("cvt.rna.tf32.f32 %0, %1;" : "=r"(r) : "f"(f));
    return r;
}
__device__ __forceinline__ float tf32r(float f) { return __uint_as_float(f2tf32(f)); }

// ---------------------------------------------------------------------------
__global__ void zero_icnt_kernel() {
    int i = blockIdx.x * blockDim.x + threadIdx.x;
    if (i < DEG_TOT / 4) ((int4*)g_icnt)[i] = make_int4(0, 0, 0, 0);
}

__global__ void round_w_kernel(const float* __restrict__ W1, const float* __restrict__ W2) {
    int i = blockIdx.x * blockDim.x + threadIdx.x;
    if (i < FIN * FHID) g_wr1[i] = tf32r(W1[i]);
    if (i < FHID * FOUT) g_wr2[i] = tf32r(W2[i]);
}

__global__ void degree_kernel(const int* __restrict__ s1, const int* __restrict__ d1,
                              const int* __restrict__ s2, const int* __restrict__ d2) {
    int i = blockIdx.x * blockDim.x + threadIdx.x;
    if (i < E1c) {
        atomicAdd(&g_icnt[OFF_OUT1 + s1[i]], 1);
        atomicAdd(&g_icnt[OFF_IN1 + d1[i]], 1);
    }
    if (i < E2c) {
        atomicAdd(&g_icnt[OFF_OUT2 + s2[i]], 1);
        atomicAdd(&g_icnt[OFF_IN2 + d2[i]], 1);
    }
}

__global__ void convert_deg_kernel() {
    int i = blockIdx.x * blockDim.x + threadIdx.x;
    if (i < DEG_TOT) g_deg[i] = rsqrtf((float)max(g_icnt[i], 1));
}

// --- 3-pass exclusive scan of in-degree counts -> CSR offsets ---------------
__global__ __launch_bounds__(256) void scan_pass1() {
    __shared__ int sh[256];
    int b = blockIdx.x, tid = threadIdx.x;
    int v = 0;
    if (b < NB1) {
        int idx = b * 256 + tid;
        if (idx < N1c) v = g_icnt[OFF_IN1 + idx];
    } else {
        int idx = (b - NB1) * 256 + tid;
        if (idx < N2c) v = g_icnt[OFF_IN2 + idx];
    }
    sh[tid] = v;
    __syncthreads();
    for (int s = 128; s > 0; s >>= 1) {
        if (tid < s) sh[tid] += sh[tid + s];
        __syncthreads();
    }
    if (tid == 0) g_bsum[b] = sh[0];
}

__global__ __launch_bounds__(512) void scan_pass2() {
    __shared__ int sh[512];
    int tid = threadIdx.x;
    int v = (tid < NB1) ? g_bsum[tid] : 0;
    sh[tid] = v;
    __syncthreads();
    for (int s = 1; s < 512; s <<= 1) {
        int a = (tid >= s) ? sh[tid - s] : 0;
        __syncthreads();
        sh[tid] += a;
        __syncthreads();
    }
    if (tid < NB1) g_boff[tid] = sh[tid] - v;
    __syncthreads();
    int v2 = (tid < NB2) ? g_bsum[NB1 + tid] : 0;
    sh[tid] = v2;
    __syncthreads();
    for (int s = 1; s < 512; s <<= 1) {
        int a = (tid >= s) ? sh[tid - s] : 0;
        __syncthreads();
        sh[tid] += a;
        __syncthreads();
    }
    if (tid < NB2) g_boff[NB1 + tid] = sh[tid] - v2;
}

__global__ __launch_bounds__(256) void scan_pass3() {
    __shared__ int sh[256];
    int b = blockIdx.x, tid = threadIdx.x;
    int v = 0, idx = 0;
    bool g1 = (b < NB1);
    if (g1) {
        idx = b * 256 + tid;
        if (idx < N1c) v = g_icnt[OFF_IN1 + idx];
    } else {
        idx = (b - NB1) * 256 + tid;
        if (idx < N2c) v = g_icnt[OFF_IN2 + idx];
    }
    sh[tid] = v;
    __syncthreads();
    for (int s = 1; s < 256; s <<= 1) {
        int a = (tid >= s) ? sh[tid - s] : 0;
        __syncthreads();
        sh[tid] += a;
        __syncthreads();
    }
    int excl = sh[tid] - v + g_boff[b];
    if (g1) {
        if (idx < N1c) { g_off1[idx] = excl; g_cur1[idx] = excl; }
    } else {
        if (idx < N2c) { g_off2[idx] = excl; g_cur2[idx] = excl; }
    }
    if (b == 0 && tid == 0) { g_off1[N1c] = E1c; g_off2[N2c] = E2c; }
}

// --- CSR fill (counting-sort edges by dst) ----------------------------------
__global__ void fill_kernel(const int* __restrict__ s1, const int* __restrict__ d1,
                            const int* __restrict__ s2, const int* __restrict__ d2) {
    int i = blockIdx.x * blockDim.x + threadIdx.x;
    if (i < E1c) {
        int p = atomicAdd(&g_cur1[d1[i]], 1);
        g_csr1[p] = s1[i];
    }
    if (i < E2c) {
        int p = atomicAdd(&g_cur2[d2[i]], 1);
        g_csr2[p] = s2[i];
    }
}

// --- Gather-aggregate layer 1 (output tf32-rounded for GEMM1) ---------------
__global__ __launch_bounds__(256) void agg1_kernel(const float* __restrict__ X) {
    int w = (blockIdx.x * blockDim.x + threadIdx.x) >> 5;
    if (w >= N1c) return;
    int lane = threadIdx.x & 31;
    int i = g_off1[w], end = g_off1[w + 1];
    float4 acc = make_float4(0.f, 0.f, 0.f, 0.f);
    const float4* X4 = (const float4*)X;
    for (; i + 1 < end; i += 2) {
        int s0 = g_csr1[i], s1 = g_csr1[i + 1];
        float c0 = g_deg[OFF_OUT1 + s0], c1 = g_deg[OFF_OUT1 + s1];
        float4 v0 = X4[(size_t)s0 * 32 + lane];
        float4 v1 = X4[(size_t)s1 * 32 + lane];
        acc.x += v0.x * c0 + v1.x * c1;
        acc.y += v0.y * c0 + v1.y * c1;
        acc.z += v0.z * c0 + v1.z * c1;
        acc.w += v0.w * c0 + v1.w * c1;
    }
    if (i < end) {
        int s0 = g_csr1[i];
        float c0 = g_deg[OFF_OUT1 + s0];
        float4 v0 = X4[(size_t)s0 * 32 + lane];
        acc.x += v0.x * c0; acc.y += v0.y * c0;
        acc.z += v0.z * c0; acc.w += v0.w * c0;
    }
    acc.x = tf32r(acc.x); acc.y = tf32r(acc.y);
    acc.z = tf32r(acc.z); acc.w = tf32r(acc.w);
    ((float4*)g_agg1)[(size_t)w * 32 + lane] = acc;
}

// --- Gather-aggregate layer 2 + fused epilogue ------------------------------
__global__ __launch_bounds__(256) void agg2_kernel(const float* __restrict__ Y,
                                                   const float* __restrict__ bias,
                                                   float* __restrict__ OUT) {
    int w = (blockIdx.x * blockDim.x + threadIdx.x) >> 5;
    if (w >= N2c) return;
    int lane = threadIdx.x & 31;
    int i = g_off2[w], end = g_off2[w + 1];
    float4 acc = make_float4(0.f, 0.f, 0.f, 0.f);
    const float4* Y4 = (const float4*)Y;
    for (; i + 1 < end; i += 2) {
        int s0 = g_csr2[i], s1 = g_csr2[i + 1];
        float4 v0 = Y4[(size_t)s0 * 32 + lane];
        float4 v1 = Y4[(size_t)s1 * 32 + lane];
        acc.x += v0.x + v1.x; acc.y += v0.y + v1.y;
        acc.z += v0.z + v1.z; acc.w += v0.w + v1.w;
    }
    if (i < end) {
        int s0 = g_csr2[i];
        float4 v0 = Y4[(size_t)s0 * 32 + lane];
        acc.x += v0.x; acc.y += v0.y; acc.z += v0.z; acc.w += v0.w;
    }
    float s = g_deg[OFF_IN2 + w];
    float4 b = ((const float4*)bias)[lane];
    acc.x = fmaxf(fmaf(acc.x, s, b.x), 0.f);
    acc.y = fmaxf(fmaf(acc.y, s, b.y), 0.f);
    acc.z = fmaxf(fmaf(acc.z, s, b.z), 0.f);
    acc.w = fmaxf(fmaf(acc.w, s, b.w), 0.f);
    ((float4*)OUT)[(size_t)w * 32 + lane] = acc;
}

// ---------------------------------------------------------------------------
// TF32 GEMM v2: cp.async double-buffered, inputs pre-rounded to tf32.
// BM=128, BN=128, BK=32, 256 threads, warp grid 4(M) x 2(N), warp tile 32x64.
// ---------------------------------------------------------------------------
#define AS_STRIDE 36
#define BS_STRIDE 132
#define SMEM_A_ELEMS (128 * AS_STRIDE)
#define SMEM_B_ELEMS (32 * BS_STRIDE)
#define SMEM_GEMM ((2 * SMEM_A_ELEMS + 2 * SMEM_B_ELEMS) * 4)

__device__ __forceinline__ uint32_t smem_u32(const void* p) {
    return (uint32_t)__cvta_generic_to_shared(p);
}
__device__ __forceinline__ void cp16(uint32_t dst, const void* src, int src_bytes) {
    asm volatile("cp.async.cg.shared.global [%0], [%1], 16, %2;"
                 :: "r"(dst), "l"(src), "r"(src_bytes));
}

__device__ __forceinline__ void mma_tf32(float c[4], const uint32_t a[4], const uint32_t b[2]) {
    asm volatile(
        "mma.sync.aligned.m16n8k8.row.col.f32.tf32.tf32.f32 "
        "{%0,%1,%2,%3}, {%4,%5,%6,%7}, {%8,%9}, {%0,%1,%2,%3};"
        : "+f"(c[0]), "+f"(c[1]), "+f"(c[2]), "+f"(c[3])
        : "r"(a[0]), "r"(a[1]), "r"(a[2]), "r"(a[3]), "r"(b[0]), "r"(b[1]));
}

__global__ __launch_bounds__(256) void gemm_tf32_ca(
    const float* __restrict__ A, const float* __restrict__ B, float* __restrict__ C,
    int M, int N, int K,
    const float* __restrict__ rowscale, const float* __restrict__ bias,
    int do_relu, int round_out)
{
    extern __shared__ float sm[];
    float (*As)[128][AS_STRIDE] = (float (*)[128][AS_STRIDE])sm;
    float (*Bs)[32][BS_STRIDE]  = (float (*)[32][BS_STRIDE])(sm + 2 * SMEM_A_ELEMS);

    int tid = threadIdx.x;
    int wid = tid >> 5, lane = tid & 31;
    int g = lane >> 2, tig = lane & 3;
    int warp_m = (wid & 3) * 32;
    int warp_n = (wid >> 2) * 64;
    int rowBase = blockIdx.y * 128;
    int colBase = blockIdx.x * 128;

    float c[2][8][4];
#pragma unroll
    for (int mi = 0; mi < 2; mi++)
#pragma unroll
        for (int ni = 0; ni < 8; ni++)
#pragma unroll
            for (int q = 0; q < 4; q++) c[mi][ni][q] = 0.f;

    // cp.async tile loader: A 128x32, B 32x128, 4 x 16B per thread each
    auto load_tile = [&](int t, int buf) {
#pragma unroll
        for (int i = 0; i < 4; i++) {
            int f4 = tid + 256 * i;
            int arow = f4 >> 3, acol = (f4 & 7) * 4;
            int gr = rowBase + arow;
            const float* asrc = &A[(size_t)(gr < M ? gr : 0) * K + t * 32 + acol];
            cp16(smem_u32(&As[buf][arow][acol]), asrc, gr < M ? 16 : 0);
            int brow = f4 >> 5, bcol = (f4 & 31) * 4;
            cp16(smem_u32(&Bs[buf][brow][bcol]),
                 &B[(size_t)(t * 32 + brow) * N + colBase + bcol], 16);
        }
        asm volatile("cp.async.commit_group;" ::: "memory");
    };

    int ntiles = K >> 5;
    load_tile(0, 0);

    for (int t = 0; t < ntiles; t++) {
        asm volatile("cp.async.wait_group 0;" ::: "memory");
        __syncthreads();
        if (t + 1 < ntiles) load_tile(t + 1, (t + 1) & 1);
        int buf = t & 1;

#pragma unroll
        for (int kk = 0; kk < 32; kk += 8) {
            uint32_t af[2][4], bf[8][2];
#pragma unroll
            for (int mi = 0; mi < 2; mi++) {
                int m = warp_m + mi * 16 + g;
                af[mi][0] = __float_as_uint(As[buf][m][kk + tig]);
                af[mi][1] = __float_as_uint(As[buf][m + 8][kk + tig]);
                af[mi][2] = __float_as_uint(As[buf][m][kk + tig + 4]);
                af[mi][3] = __float_as_uint(As[buf][m + 8][kk + tig + 4]);
            }
#pragma unroll
            for (int ni = 0; ni < 8; ni++) {
                int n = warp_n + ni * 8 + g;
                bf[ni][0] = __float_as_uint(Bs[buf][kk + tig][n]);
                bf[ni][1] = __float_as_uint(Bs[buf][kk + tig + 4][n]);
            }
#pragma unroll
            for (int mi = 0; mi < 2; mi++)
#pragma unroll
                for (int ni = 0; ni < 8; ni++)
                    mma_tf32(c[mi][ni], af[mi], bf[ni]);
        }
    }

    // Epilogue: rowscale * acc + bias, optional relu, optional tf32 rounding
#pragma unroll
    for (int mi = 0; mi < 2; mi++) {
#pragma unroll
        for (int half = 0; half < 2; half++) {
            int row = rowBase + warp_m + mi * 16 + g + half * 8;
            if (row >= M) continue;
            float s = rowscale ? rowscale[row] : 1.f;
#pragma unroll
            for (int ni = 0; ni < 8; ni++) {
                int col = colBase + warp_n + ni * 8 + 2 * tig;
                float v0 = c[mi][ni][half * 2 + 0] * s;
                float v1 = c[mi][ni][half * 2 + 1] * s;
                if (bias) { v0 += bias[col]; v1 += bias[col + 1]; }
                if (do_relu) { v0 = fmaxf(v0, 0.f); v1 = fmaxf(v1, 0.f); }
                if (round_out) { v0 = tf32r(v0); v1 = tf32r(v1); }
                *(float2*)&C[(size_t)row * N + col] = make_float2(v0, v1);
            }
        }
    }
}

// ---------------------------------------------------------------------------
extern "C" void kernel_launch(void* const* d_in, const int* in_sizes, int n_in,
                              void* d_out, int out_size) {
    const float* x   = (const float*)d_in[0];
    const float* W1  = (const float*)d_in[1];
    const float* b1  = (const float*)d_in[2];
    const float* W2  = (const float*)d_in[3];
    const float* b2  = (const float*)d_in[4];
    const int* src1  = (const int*)d_in[5];
    const int* dst1  = (const int*)d_in[6];
    const int* src2  = (const int*)d_in[7];
    const int* dst2  = (const int*)d_in[8];
    float* out = (float*)d_out;

    float *deg, *agg1, *h, *y, *wr1, *wr2;
    cudaGetSymbolAddress((void**)&deg, g_deg);
    cudaGetSymbolAddress((void**)&agg1, g_agg1);
    cudaGetSymbolAddress((void**)&h, g_h);
    cudaGetSymbolAddress((void**)&y, g_y);
    cudaGetSymbolAddress((void**)&wr1, g_wr1);
    cudaGetSymbolAddress((void**)&wr2, g_wr2);

    cudaFuncSetAttribute(gemm_tf32_ca, cudaFuncAttributeMaxDynamicSharedMemorySize, SMEM_GEMM);

    const int TB = 256;

    // Degrees (int counts) + CSR build + weight rounding
    zero_icnt_kernel<<<(DEG_TOT / 4 + TB - 1) / TB, TB>>>();
    round_w_kernel<<<(FIN * FHID + TB - 1) / TB, TB>>>(W1, W2);
    degree_kernel<<<(E1c + TB - 1) / TB, TB>>>(src1, dst1, src2, dst2);
    scan_pass1<<<NBT, 256>>>();
    scan_pass2<<<1, 512>>>();
    scan_pass3<<<NBT, 256>>>();
    convert_deg_kernel<<<(DEG_TOT + TB - 1) / TB, TB>>>();
    fill_kernel<<<(E1c + TB - 1) / TB, TB>>>(src1, dst1, src2, dst2);

    // Layer 1 aggregate (CSR gather): agg1 = tf32( segsum(x * outdeg1^-1/2) )
    agg1_kernel<<<(N1c * 32 + TB - 1) / TB, TB>>>(x);

    // h = tf32( relu( indeg1inv[m] * agg1 @ W1r + b1 ) )
    {
        dim3 grid(FHID / 128, (N1c + 127) / 128);
        gemm_tf32_ca<<<grid, 256, SMEM_GEMM>>>(agg1, wr1, h, N1c, FHID, FIN,
                                               deg + OFF_IN1, b1, 1, 1);
    }
    // y = outdeg2inv[m] * (h @ W2r)
    {
        dim3 grid(FOUT / 128, (N1c + 127) / 128);
        gemm_tf32_ca<<<grid, 256, SMEM_GEMM>>>(h, wr2, y, N1c, FOUT, FHID,
                                               deg + OFF_OUT2, nullptr, 0, 0);
    }
    // Layer 2 aggregate + fused scale/bias/relu -> out
    agg2_kernel<<<(N2c * 32 + TB - 1) / TB, TB>>>(y, b2, out);
}

// round 6
// speedup vs baseline: 2.4735x; 1.1225x over previous
#include <cuda_runtime.h>
#include <cuda_fp16.h>
#include <cstdint>
#include <cstddef>
#include <cstring>

// Problem constants (fixed-shape problem)
#define N0c 200000
#define N1c 100000
#define N2c 50000
#define E1c 1600000
#define E2c 800000
#define FIN 128
#define FHID 256
#define FOUT 128

// degree/count layout: [0,N0) out1 | [N0,+N1) in1 | [+N1) out2 | [+N2) in2
#define OFF_OUT1 0
#define OFF_IN1  200000
#define OFF_OUT2 300000
#define OFF_IN2  400000
#define DEG_TOT  450000

#define NB1 ((N1c + 255) / 256)   // 391
#define NB2 ((N2c + 255) / 256)   // 196
#define NBT (NB1 + NB2)           // 587

// Scratch (no allocations allowed)
__device__ int    g_icnt[DEG_TOT];
__device__ float  g_deg[DEG_TOT];
__device__ int    g_off1[N1c + 1];
__device__ int    g_cur1[N1c];
__device__ int    g_off2[N2c + 1];
__device__ int    g_cur2[N2c];
__device__ int    g_csr1[E1c];
__device__ int    g_csr2[E2c];
__device__ int    g_bsum[1024];
__device__ int    g_boff[1024];
__device__ float  g_wr1[FIN * FHID];            // tf32-rounded W1
__device__ float  g_wr2[FHID * FOUT];           // tf32-rounded W2
__device__ uint2  g_xh[(size_t)N0c * 32];       // fp16 pre-scaled X, 51.2 MB
__device__ float  g_agg1[(size_t)N1c * FIN];    // 51.2 MB (tf32-rounded)
__device__ __half g_y16[(size_t)N1c * FOUT];    // 25.6 MB

__device__ __forceinline__ uint32_t f2tf32(float f) {
    uint32_t r;
    asm("cvt.rna.tf32.f32 %0, %1;" : "=r"(r) : "f"(f));
    return r;
}
__device__ __forceinline__ float tf32r(float f) { return __uint_as_float(f2tf32(f)); }

__device__ __forceinline__ uint32_t h2_as_u32(__half2 h) {
    uint32_t u; memcpy(&u, &h, 4); return u;
}
__device__ __forceinline__ __half2 u32_as_h2(uint32_t u) {
    __half2 h; memcpy(&h, &u, 4); return h;
}

// ---------------------------------------------------------------------------
__global__ void prep_kernel(const float* __restrict__ W1, const float* __restrict__ W2) {
    int i = blockIdx.x * blockDim.x + threadIdx.x;
    if (i < DEG_TOT / 4) ((int4*)g_icnt)[i] = make_int4(0, 0, 0, 0);
    if (i < FIN * FHID) g_wr1[i] = tf32r(W1[i]);
    if (i < FHID * FOUT) g_wr2[i] = tf32r(W2[i]);
}

__global__ void degree_kernel(const int* __restrict__ s1, const int* __restrict__ d1,
                              const int* __restrict__ s2, const int* __restrict__ d2) {
    int i = blockIdx.x * blockDim.x + threadIdx.x;
    if (i < E1c) {
        atomicAdd(&g_icnt[OFF_OUT1 + s1[i]], 1);
        atomicAdd(&g_icnt[OFF_IN1 + d1[i]], 1);
    }
    if (i < E2c) {
        atomicAdd(&g_icnt[OFF_OUT2 + s2[i]], 1);
        atomicAdd(&g_icnt[OFF_IN2 + d2[i]], 1);
    }
}

__global__ void convert_deg_kernel() {
    int i = blockIdx.x * blockDim.x + threadIdx.x;
    if (i < DEG_TOT) g_deg[i] = rsqrtf((float)max(g_icnt[i], 1));
}

// X -> fp16, pre-scaled by outdeg1^-1/2 (per source row)
__global__ void convert_x_kernel(const float* __restrict__ X) {
    int i = blockIdx.x * blockDim.x + threadIdx.x;
    if (i >= N0c * 32) return;
    int row = i >> 5;
    float c = g_deg[OFF_OUT1 + row];
    float4 v = ((const float4*)X)[i];
    uint2 o;
    o.x = h2_as_u32(__floats2half2_rn(v.x * c, v.y * c));
    o.y = h2_as_u32(__floats2half2_rn(v.z * c, v.w * c));
    g_xh[i] = o;
}

// --- 3-pass exclusive scan of in-degree counts -> CSR offsets ---------------
__global__ __launch_bounds__(256) void scan_pass1() {
    __shared__ int sh[256];
    int b = blockIdx.x, tid = threadIdx.x;
    int v = 0;
    if (b < NB1) {
        int idx = b * 256 + tid;
        if (idx < N1c) v = g_icnt[OFF_IN1 + idx];
    } else {
        int idx = (b - NB1) * 256 + tid;
        if (idx < N2c) v = g_icnt[OFF_IN2 + idx];
    }
    sh[tid] = v;
    __syncthreads();
    for (int s = 128; s > 0; s >>= 1) {
        if (tid < s) sh[tid] += sh[tid + s];
        __syncthreads();
    }
    if (tid == 0) g_bsum[b] = sh[0];
}

__global__ __launch_bounds__(512) void scan_pass2() {
    __shared__ int sh[512];
    int tid = threadIdx.x;
    int v = (tid < NB1) ? g_bsum[tid] : 0;
    sh[tid] = v;
    __syncthreads();
    for (int s = 1; s < 512; s <<= 1) {
        int a = (tid >= s) ? sh[tid - s] : 0;
        __syncthreads();
        sh[tid] += a;
        __syncthreads();
    }
    if (tid < NB1) g_boff[tid] = sh[tid] - v;
    __syncthreads();
    int v2 = (tid < NB2) ? g_bsum[NB1 + tid] : 0;
    sh[tid] = v2;
    __syncthreads();
    for (int s = 1; s < 512; s <<= 1) {
        int a = (tid >= s) ? sh[tid - s] : 0;
        __syncthreads();
        sh[tid] += a;
        __syncthreads();
    }
    if (tid < NB2) g_boff[NB1 + tid] = sh[tid] - v2;
}

__global__ __launch_bounds__(256) void scan_pass3() {
    __shared__ int sh[256];
    int b = blockIdx.x, tid = threadIdx.x;
    int v = 0, idx = 0;
    bool g1 = (b < NB1);
    if (g1) {
        idx = b * 256 + tid;
        if (idx < N1c) v = g_icnt[OFF_IN1 + idx];
    } else {
        idx = (b - NB1) * 256 + tid;
        if (idx < N2c) v = g_icnt[OFF_IN2 + idx];
    }
    sh[tid] = v;
    __syncthreads();
    for (int s = 1; s < 256; s <<= 1) {
        int a = (tid >= s) ? sh[tid - s] : 0;
        __syncthreads();
        sh[tid] += a;
        __syncthreads();
    }
    int excl = sh[tid] - v + g_boff[b];
    if (g1) {
        if (idx < N1c) { g_off1[idx] = excl; g_cur1[idx] = excl; }
    } else {
        if (idx < N2c) { g_off2[idx] = excl; g_cur2[idx] = excl; }
    }
    if (b == 0 && tid == 0) { g_off1[N1c] = E1c; g_off2[N2c] = E2c; }
}

// --- CSR fill (counting-sort edges by dst) ----------------------------------
__global__ void fill_kernel(const int* __restrict__ s1, const int* __restrict__ d1,
                            const int* __restrict__ s2, const int* __restrict__ d2) {
    int i = blockIdx.x * blockDim.x + threadIdx.x;
    if (i < E1c) {
        int p = atomicAdd(&g_cur1[d1[i]], 1);
        g_csr1[p] = s1[i];
    }
    if (i < E2c) {
        int p = atomicAdd(&g_cur2[d2[i]], 1);
        g_csr2[p] = s2[i];
    }
}

// --- Layer-1 aggregate: fp16 gather, fp32 accumulate, tf32-rounded output ---
__global__ __launch_bounds__(256) void agg1_kernel() {
    int w = (blockIdx.x * blockDim.x + threadIdx.x) >> 5;
    if (w >= N1c) return;
    int lane = threadIdx.x & 31;
    int i = g_off1[w], end = g_off1[w + 1];
    float4 acc = make_float4(0.f, 0.f, 0.f, 0.f);
    for (; i + 1 < end; i += 2) {
        int s0 = g_csr1[i], s1 = g_csr1[i + 1];
        uint2 u0 = g_xh[(size_t)s0 * 32 + lane];
        uint2 u1 = g_xh[(size_t)s1 * 32 + lane];
        float2 a0 = __half22float2(u32_as_h2(u0.x));
        float2 b0 = __half22float2(u32_as_h2(u0.y));
        float2 a1 = __half22float2(u32_as_h2(u1.x));
        float2 b1 = __half22float2(u32_as_h2(u1.y));
        acc.x += a0.x + a1.x; acc.y += a0.y + a1.y;
        acc.z += b0.x + b1.x; acc.w += b0.y + b1.y;
    }
    if (i < end) {
        int s0 = g_csr1[i];
        uint2 u0 = g_xh[(size_t)s0 * 32 + lane];
        float2 a0 = __half22float2(u32_as_h2(u0.x));
        float2 b0 = __half22float2(u32_as_h2(u0.y));
        acc.x += a0.x; acc.y += a0.y; acc.z += b0.x; acc.w += b0.y;
    }
    acc.x = tf32r(acc.x); acc.y = tf32r(acc.y);
    acc.z = tf32r(acc.z); acc.w = tf32r(acc.w);
    ((float4*)g_agg1)[(size_t)w * 32 + lane] = acc;
}

// --- Layer-2 aggregate (fp16 gather) + fused scale/bias/relu ----------------
__global__ __launch_bounds__(256) void agg2_kernel(const float* __restrict__ bias,
                                                   float* __restrict__ OUT) {
    int w = (blockIdx.x * blockDim.x + threadIdx.x) >> 5;
    if (w >= N2c) return;
    int lane = threadIdx.x & 31;
    int i = g_off2[w], end = g_off2[w + 1];
    float4 acc = make_float4(0.f, 0.f, 0.f, 0.f);
    const uint2* Y2 = (const uint2*)g_y16;
    for (; i + 1 < end; i += 2) {
        int s0 = g_csr2[i], s1 = g_csr2[i + 1];
        uint2 u0 = Y2[(size_t)s0 * 32 + lane];
        uint2 u1 = Y2[(size_t)s1 * 32 + lane];
        float2 a0 = __half22float2(u32_as_h2(u0.x));
        float2 b0 = __half22float2(u32_as_h2(u0.y));
        float2 a1 = __half22float2(u32_as_h2(u1.x));
        float2 b1 = __half22float2(u32_as_h2(u1.y));
        acc.x += a0.x + a1.x; acc.y += a0.y + a1.y;
        acc.z += b0.x + b1.x; acc.w += b0.y + b1.y;
    }
    if (i < end) {
        int s0 = g_csr2[i];
        uint2 u0 = Y2[(size_t)s0 * 32 + lane];
        float2 a0 = __half22float2(u32_as_h2(u0.x));
        float2 b0 = __half22float2(u32_as_h2(u0.y));
        acc.x += a0.x; acc.y += a0.y; acc.z += b0.x; acc.w += b0.y;
    }
    float s = g_deg[OFF_IN2 + w];
    float4 b = ((const float4*)bias)[lane];
    acc.x = fmaxf(fmaf(acc.x, s, b.x), 0.f);
    acc.y = fmaxf(fmaf(acc.y, s, b.y), 0.f);
    acc.z = fmaxf(fmaf(acc.z, s, b.z), 0.f);
    acc.w = fmaxf(fmaf(acc.w, s, b.w), 0.f);
    ((float4*)OUT)[(size_t)w * 32 + lane] = acc;
}

// ---------------------------------------------------------------------------
// Fused MLP: per 128-row CTA:
//   Stage A (x2 n-passes): Hs[128][256] = tf32(relu(rs1*agg1@W1 + b1)) in SMEM
//   Stage B: y[128][128] = fp16(rs2 * Hs@W2), A-fragments straight from SMEM.
// ---------------------------------------------------------------------------
#define HS_STRIDE 260
#define AS_STRIDE 36
#define BS_STRIDE 136
#define HS_ELEMS (128 * HS_STRIDE)
#define AS_ELEMS (128 * AS_STRIDE)
#define BS_ELEMS (32 * BS_STRIDE)
#define SMEM_FUSED ((HS_ELEMS + 2 * AS_ELEMS + 2 * BS_ELEMS) * 4)

__device__ __forceinline__ uint32_t smem_u32(const void* p) {
    return (uint32_t)__cvta_generic_to_shared(p);
}
__device__ __forceinline__ void cp16(uint32_t dst, const void* src, int src_bytes) {
    asm volatile("cp.async.cg.shared.global [%0], [%1], 16, %2;"
                 :: "r"(dst), "l"(src), "r"(src_bytes));
}
__device__ __forceinline__ void mma_tf32(float c[4], const uint32_t a[4], const uint32_t b[2]) {
    asm volatile(
        "mma.sync.aligned.m16n8k8.row.col.f32.tf32.tf32.f32 "
        "{%0,%1,%2,%3}, {%4,%5,%6,%7}, {%8,%9}, {%0,%1,%2,%3};"
        : "+f"(c[0]), "+f"(c[1]), "+f"(c[2]), "+f"(c[3])
        : "r"(a[0]), "r"(a[1]), "r"(a[2]), "r"(a[3]), "r"(b[0]), "r"(b[1]));
}

__global__ __launch_bounds__(256) void fused_gemm(
    const float* __restrict__ A,     // agg1 [M,128] (tf32 values)
    const float* __restrict__ W1r,   // [128,256]
    const float* __restrict__ W2r,   // [256,128]
    __half* __restrict__ Y,          // [M,128]
    const float* __restrict__ rs1, const float* __restrict__ b1,
    const float* __restrict__ rs2, int M)
{
    extern __shared__ float sm[];
    float (*Hs)[HS_STRIDE]       = (float (*)[HS_STRIDE])sm;
    float (*Ast)[128][AS_STRIDE] = (float (*)[128][AS_STRIDE])(sm + HS_ELEMS);
    float (*Bst)[32][BS_STRIDE]  = (float (*)[32][BS_STRIDE])(sm + HS_ELEMS + 2 * AS_ELEMS);

    int tid = threadIdx.x;
    int wid = tid >> 5, lane = tid & 31;
    int g = lane >> 2, tig = lane & 3;
    int warp_m = (wid & 3) * 32;
    int warp_n = (wid >> 2) * 64;
    int rowBase = blockIdx.x * 128;

    // A-tile loader (agg1, row stride 128 floats)
    auto loadA = [&](int t, int buf) {
#pragma unroll
        for (int i = 0; i < 4; i++) {
            int f4 = tid + 256 * i;
            int arow = f4 >> 3, acol = (f4 & 7) * 4;
            int gr = rowBase + arow;
            cp16(smem_u32(&Ast[buf][arow][acol]),
                 &A[(size_t)(gr < M ? gr : 0) * FIN + t * 32 + acol], gr < M ? 16 : 0);
        }
    };
    // B-tile loader (weight matrix, configurable row stride / column offset)
    auto loadB = [&](const float* Bp, int ldb, int cb, int t, int buf) {
#pragma unroll
        for (int i = 0; i < 4; i++) {
            int f4 = tid + 256 * i;
            int brow = f4 >> 5, bcol = (f4 & 31) * 4;
            cp16(smem_u32(&Bst[buf][brow][bcol]),
                 &Bp[(size_t)(t * 32 + brow) * ldb + cb + bcol], 16);
        }
    };

    // ---------------- Stage A: two 128x128 n-passes over W1 ----------------
#pragma unroll 1
    for (int pass = 0; pass < 2; pass++) {
        int cb = pass * 128;
        float c[2][8][4];
#pragma unroll
        for (int mi = 0; mi < 2; mi++)
#pragma unroll
            for (int ni = 0; ni < 8; ni++)
#pragma unroll
                for (int q = 0; q < 4; q++) c[mi][ni][q] = 0.f;

        loadA(0, 0);
        loadB(W1r, FHID, cb, 0, 0);
        asm volatile("cp.async.commit_group;" ::: "memory");

#pragma unroll 1
        for (int t = 0; t < 4; t++) {
            asm volatile("cp.async.wait_group 0;" ::: "memory");
            __syncthreads();
            if (t < 3) {
                loadA(t + 1, (t + 1) & 1);
                loadB(W1r, FHID, cb, t + 1, (t + 1) & 1);
                asm volatile("cp.async.commit_group;" ::: "memory");
            }
            int buf = t & 1;
#pragma unroll
            for (int kk = 0; kk < 32; kk += 8) {
                uint32_t af[2][4], bf[8][2];
#pragma unroll
                for (int mi = 0; mi < 2; mi++) {
                    int m = warp_m + mi * 16 + g;
                    af[mi][0] = __float_as_uint(Ast[buf][m][kk + tig]);
                    af[mi][1] = __float_as_uint(Ast[buf][m + 8][kk + tig]);
                    af[mi][2] = __float_as_uint(Ast[buf][m][kk + tig + 4]);
                    af[mi][3] = __float_as_uint(Ast[buf][m + 8][kk + tig + 4]);
                }
#pragma unroll
                for (int ni = 0; ni < 8; ni++) {
                    int n = warp_n + ni * 8 + g;
                    bf[ni][0] = __float_as_uint(Bst[buf][kk + tig][n]);
                    bf[ni][1] = __float_as_uint(Bst[buf][kk + tig + 4][n]);
                }
#pragma unroll
                for (int mi = 0; mi < 2; mi++)
#pragma unroll
                    for (int ni = 0; ni < 8; ni++)
                        mma_tf32(c[mi][ni], af[mi], bf[ni]);
            }
        }

        // Epilogue -> Hs (scale, bias, relu, tf32 round)
#pragma unroll
        for (int mi = 0; mi < 2; mi++) {
#pragma unroll
            for (int half = 0; half < 2; half++) {
                int rl = warp_m + mi * 16 + g + half * 8;
                int row = rowBase + rl;
                float s = (row < M) ? rs1[row] : 0.f;
#pragma unroll
                for (int ni = 0; ni < 8; ni++) {
                    int col = cb + warp_n + ni * 8 + 2 * tig;
                    float v0 = 0.f, v1 = 0.f;
                    if (row < M) {
                        v0 = tf32r(fmaxf(c[mi][ni][half * 2 + 0] * s + b1[col], 0.f));
                        v1 = tf32r(fmaxf(c[mi][ni][half * 2 + 1] * s + b1[col + 1], 0.f));
                    }
                    *(float2*)&Hs[rl][col] = make_float2(v0, v1);
                }
            }
        }
    }

    // ---------------- Stage B: y = Hs @ W2 (K=256) -------------------------
    float c2[2][8][4];
#pragma unroll
    for (int mi = 0; mi < 2; mi++)
#pragma unroll
        for (int ni = 0; ni < 8; ni++)
#pragma unroll
            for (int q = 0; q < 4; q++) c2[mi][ni][q] = 0.f;

    loadB(W2r, FOUT, 0, 0, 0);
    asm volatile("cp.async.commit_group;" ::: "memory");

#pragma unroll 1
    for (int t = 0; t < 8; t++) {
        asm volatile("cp.async.wait_group 0;" ::: "memory");
        __syncthreads();   // t=0: also publishes the Hs writes from stage A
        if (t < 7) {
            loadB(W2r, FOUT, 0, t + 1, (t + 1) & 1);
            asm volatile("cp.async.commit_group;" ::: "memory");
        }
        int buf = t & 1;
#pragma unroll
        for (int kk = 0; kk < 32; kk += 8) {
            uint32_t af[2][4], bf[8][2];
            int kbase = t * 32 + kk;
#pragma unroll
            for (int mi = 0; mi < 2; mi++) {
                int m = warp_m + mi * 16 + g;
                af[mi][0] = __float_as_uint(Hs[m][kbase + tig]);
                af[mi][1] = __float_as_uint(Hs[m + 8][kbase + tig]);
                af[mi][2] = __float_as_uint(Hs[m][kbase + tig + 4]);
                af[mi][3] = __float_as_uint(Hs[m + 8][kbase + tig + 4]);
            }
#pragma unroll
            for (int ni = 0; ni < 8; ni++) {
                int n = warp_n + ni * 8 + g;
                bf[ni][0] = __float_as_uint(Bst[buf][kk + tig][n]);
                bf[ni][1] = __float_as_uint(Bst[buf][kk + tig + 4][n]);
            }
#pragma unroll
            for (int mi = 0; mi < 2; mi++)
#pragma unroll
                for (int ni = 0; ni < 8; ni++)
                    mma_tf32(c2[mi][ni], af[mi], bf[ni]);
        }
    }

    // Epilogue -> Y (fp16, pre-scaled by outdeg2^-1/2)
#pragma unroll
    for (int mi = 0; mi < 2; mi++) {
#pragma unroll
        for (int half = 0; half < 2; half++) {
            int row = rowBase + warp_m + mi * 16 + g + half * 8;
            if (row >= M) continue;
            float s = rs2[row];
#pragma unroll
            for (int ni = 0; ni < 8; ni++) {
                int col = warp_n + ni * 8 + 2 * tig;
                __half2 h2 = __floats2half2_rn(c2[mi][ni][half * 2 + 0] * s,
                                               c2[mi][ni][half * 2 + 1] * s);
                *(__half2*)&Y[(size_t)row * FOUT + col] = h2;
            }
        }
    }
}

// ---------------------------------------------------------------------------
extern "C" void kernel_launch(void* const* d_in, const int* in_sizes, int n_in,
                              void* d_out, int out_size) {
    const float* x   = (const float*)d_in[0];
    const float* W1  = (const float*)d_in[1];
    const float* b1  = (const float*)d_in[2];
    const float* W2  = (const float*)d_in[3];
    const float* b2  = (const float*)d_in[4];
    const int* src1  = (const int*)d_in[5];
    const int* dst1  = (const int*)d_in[6];
    const int* src2  = (const int*)d_in[7];
    const int* dst2  = (const int*)d_in[8];
    float* out = (float*)d_out;

    float *deg, *agg1, *wr1, *wr2;
    __half* y16;
    cudaGetSymbolAddress((void**)&deg, g_deg);
    cudaGetSymbolAddress((void**)&agg1, g_agg1);
    cudaGetSymbolAddress((void**)&wr1, g_wr1);
    cudaGetSymbolAddress((void**)&wr2, g_wr2);
    cudaGetSymbolAddress((void**)&y16, g_y16);

    cudaFuncSetAttribute(fused_gemm, cudaFuncAttributeMaxDynamicSharedMemorySize, SMEM_FUSED);

    const int TB = 256;

    // Prep (zero counts + round weights), degrees, CSR build, X conversion
    prep_kernel<<<(DEG_TOT / 4 + TB - 1) / TB, TB>>>(W1, W2);
    degree_kernel<<<(E1c + TB - 1) / TB, TB>>>(src1, dst1, src2, dst2);
    convert_deg_kernel<<<(DEG_TOT + TB - 1) / TB, TB>>>();
    convert_x_kernel<<<(N0c * 32 + TB - 1) / TB, TB>>>(x);
    scan_pass1<<<NBT, 256>>>();
    scan_pass2<<<1, 512>>>();
    scan_pass3<<<NBT, 256>>>();
    fill_kernel<<<(E1c + TB - 1) / TB, TB>>>(src1, dst1, src2, dst2);

    // Layer 1 aggregate (fp16 gather): agg1 = tf32( segsum(xh) )
    agg1_kernel<<<(N1c * 32 + TB - 1) / TB, TB>>>();

    // Fused: h = tf32(relu(rs1*agg1@W1+b1)) [smem]; y16 = fp16(rs2*(h@W2))
    fused_gemm<<<(N1c + 127) / 128, 256, SMEM_FUSED>>>(
        agg1, wr1, wr2, y16, deg + OFF_IN1, b1, deg + OFF_OUT2, N1c);

    // Layer 2 aggregate + fused scale/bias/relu -> out
    agg2_kernel<<<(N2c * 32 + TB - 1) / TB, TB>>>(b2, out);
}

// round 8
// speedup vs baseline: 3.1852x; 1.2877x over previous
#include <cuda_runtime.h>
#include <cuda_fp16.h>
#include <cstdint>
#include <cstddef>
#include <cstring>

// Problem constants (fixed-shape problem)
#define N0c 200000
#define N1c 100000
#define N2c 50000
#define E1c 1600000
#define E2c 800000
#define FIN 128
#define FHID 256
#define FOUT 128

// degree/count layout: [0,N0) out1 | [N0,+N1) in1 | [+N1) out2 | [+N2) in2
#define OFF_OUT1 0
#define OFF_IN1  200000
#define OFF_OUT2 300000
#define OFF_IN2  400000
#define DEG_TOT  450000

#define NB1 ((N1c + 255) / 256)   // 391
#define NB2 ((N2c + 255) / 256)   // 196
#define NBT (NB1 + NB2)           // 587

// Scratch (no allocations allowed)
__device__ int    g_icnt[DEG_TOT];
__device__ float  g_deg[DEG_TOT];
__device__ int    g_off1[N1c + 1];
__device__ int    g_cur1[N1c];
__device__ int    g_off2[N2c + 1];
__device__ int    g_cur2[N2c];
__device__ int    g_csr1[E1c];
__device__ int    g_csr2[E2c];
__device__ int    g_bsum[1024];
__device__ int    g_boff[1024];
__device__ __half g_w1h[FHID * FIN];            // W1^T fp16 [n][k]
__device__ __half g_w2h[FOUT * FHID];           // W2^T fp16 [n][k]
__device__ uint2  g_xh[(size_t)N0c * 32];       // fp16 pre-scaled X, 51.2 MB
__device__ uint2  g_a16[(size_t)N1c * 32];      // fp16 agg1, 25.6 MB
__device__ __half g_y16[(size_t)N1c * FOUT];    // 25.6 MB

__device__ __forceinline__ uint32_t h2_as_u32(__half2 h) {
    uint32_t u; memcpy(&u, &h, 4); return u;
}
__device__ __forceinline__ __half2 u32_as_h2(uint32_t u) {
    __half2 h; memcpy(&h, &u, 4); return h;
}

// ---------------------------------------------------------------------------
__global__ void prep_kernel(const float* __restrict__ W1, const float* __restrict__ W2) {
    int i = blockIdx.x * blockDim.x + threadIdx.x;
    if (i < DEG_TOT / 4) ((int4*)g_icnt)[i] = make_int4(0, 0, 0, 0);
    if (i < DEG_TOT - (DEG_TOT / 4) * 4) g_icnt[(DEG_TOT / 4) * 4 + i] = 0;
    if (i < FIN * FHID) {                       // W1 [k=FIN][n=FHID] -> [n][k]
        int k = i / FHID, n = i % FHID;
        g_w1h[n * FIN + k] = __float2half(W1[i]);
    }
    if (i < FHID * FOUT) {                      // W2 [k=FHID][n=FOUT] -> [n][k]
        int k = i / FOUT, n = i % FOUT;
        g_w2h[n * FHID + k] = __float2half(W2[i]);
    }
}

__global__ void degree_kernel(const int* __restrict__ s1, const int* __restrict__ d1,
                              const int* __restrict__ s2, const int* __restrict__ d2) {
    int i = blockIdx.x * blockDim.x + threadIdx.x;
    if (i < E1c) {
        atomicAdd(&g_icnt[OFF_OUT1 + s1[i]], 1);
        atomicAdd(&g_icnt[OFF_IN1 + d1[i]], 1);
    }
    if (i < E2c) {
        atomicAdd(&g_icnt[OFF_OUT2 + s2[i]], 1);
        atomicAdd(&g_icnt[OFF_IN2 + d2[i]], 1);
    }
}

__global__ void convert_deg_kernel() {
    int i = blockIdx.x * blockDim.x + threadIdx.x;
    if (i < DEG_TOT) g_deg[i] = rsqrtf((float)max(g_icnt[i], 1));
}

// X -> fp16, pre-scaled by outdeg1^-1/2 (per source row)
__global__ void convert_x_kernel(const float* __restrict__ X) {
    int i = blockIdx.x * blockDim.x + threadIdx.x;
    if (i >= N0c * 32) return;
    int row = i >> 5;
    float c = g_deg[OFF_OUT1 + row];
    float4 v = ((const float4*)X)[i];
    uint2 o;
    o.x = h2_as_u32(__floats2half2_rn(v.x * c, v.y * c));
    o.y = h2_as_u32(__floats2half2_rn(v.z * c, v.w * c));
    g_xh[i] = o;
}

// --- 3-pass exclusive scan of in-degree counts -> CSR offsets ---------------
__global__ __launch_bounds__(256) void scan_pass1() {
    __shared__ int sh[256];
    int b = blockIdx.x, tid = threadIdx.x;
    int v = 0;
    if (b < NB1) {
        int idx = b * 256 + tid;
        if (idx < N1c) v = g_icnt[OFF_IN1 + idx];
    } else {
        int idx = (b - NB1) * 256 + tid;
        if (idx < N2c) v = g_icnt[OFF_IN2 + idx];
    }
    sh[tid] = v;
    __syncthreads();
    for (int s = 128; s > 0; s >>= 1) {
        if (tid < s) sh[tid] += sh[tid + s];
        __syncthreads();
    }
    if (tid == 0) g_bsum[b] = sh[0];
}

__global__ __launch_bounds__(512) void scan_pass2() {
    __shared__ int sh[512];
    int tid = threadIdx.x;
    int v = (tid < NB1) ? g_bsum[tid] : 0;
    sh[tid] = v;
    __syncthreads();
    for (int s = 1; s < 512; s <<= 1) {
        int a = (tid >= s) ? sh[tid - s] : 0;
        __syncthreads();
        sh[tid] += a;
        __syncthreads();
    }
    if (tid < NB1) g_boff[tid] = sh[tid] - v;
    __syncthreads();
    int v2 = (tid < NB2) ? g_bsum[NB1 + tid] : 0;
    sh[tid] = v2;
    __syncthreads();
    for (int s = 1; s < 512; s <<= 1) {
        int a = (tid >= s) ? sh[tid - s] : 0;
        __syncthreads();
        sh[tid] += a;
        __syncthreads();
    }
    if (tid < NB2) g_boff[NB1 + tid] = sh[tid] - v2;
}

__global__ __launch_bounds__(256) void scan_pass3() {
    __shared__ int sh[256];
    int b = blockIdx.x, tid = threadIdx.x;
    int v = 0, idx = 0;
    bool g1 = (b < NB1);
    if (g1) {
        idx = b * 256 + tid;
        if (idx < N1c) v = g_icnt[OFF_IN1 + idx];
    } else {
        idx = (b - NB1) * 256 + tid;
        if (idx < N2c) v = g_icnt[OFF_IN2 + idx];
    }
    sh[tid] = v;
    __syncthreads();
    for (int s = 1; s < 256; s <<= 1) {
        int a = (tid >= s) ? sh[tid - s] : 0;
        __syncthreads();
        sh[tid] += a;
        __syncthreads();
    }
    int excl = sh[tid] - v + g_boff[b];
    if (g1) {
        if (idx < N1c) { g_off1[idx] = excl; g_cur1[idx] = excl; }
    } else {
        if (idx < N2c) { g_off2[idx] = excl; g_cur2[idx] = excl; }
    }
    if (b == 0 && tid == 0) { g_off1[N1c] = E1c; g_off2[N2c] = E2c; }
}

// --- CSR fill (counting-sort edges by dst) ----------------------------------
__global__ void fill_kernel(const int* __restrict__ s1, const int* __restrict__ d1,
                            const int* __restrict__ s2, const int* __restrict__ d2) {
    int i = blockIdx.x * blockDim.x + threadIdx.x;
    if (i < E1c) {
        int p = atomicAdd(&g_cur1[d1[i]], 1);
        g_csr1[p] = s1[i];
    }
    if (i < E2c) {
        int p = atomicAdd(&g_cur2[d2[i]], 1);
        g_csr2[p] = s2[i];
    }
}

// --- Layer-1 aggregate: fp16 gather, fp32 accumulate, fp16 output -----------
__global__ __launch_bounds__(256) void agg1_kernel() {
    int w = (blockIdx.x * blockDim.x + threadIdx.x) >> 5;
    if (w >= N1c) return;
    int lane = threadIdx.x & 31;
    int i = g_off1[w], end = g_off1[w + 1];
    float4 acc = make_float4(0.f, 0.f, 0.f, 0.f);
    for (; i + 1 < end; i += 2) {
        int s0 = g_csr1[i], s1 = g_csr1[i + 1];
        uint2 u0 = g_xh[(size_t)s0 * 32 + lane];
        uint2 u1 = g_xh[(size_t)s1 * 32 + lane];
        float2 a0 = __half22float2(u32_as_h2(u0.x));
        float2 b0 = __half22float2(u32_as_h2(u0.y));
        float2 a1 = __half22float2(u32_as_h2(u1.x));
        float2 b1 = __half22float2(u32_as_h2(u1.y));
        acc.x += a0.x + a1.x; acc.y += a0.y + a1.y;
        acc.z += b0.x + b1.x; acc.w += b0.y + b1.y;
    }
    if (i < end) {
        int s0 = g_csr1[i];
        uint2 u0 = g_xh[(size_t)s0 * 32 + lane];
        float2 a0 = __half22float2(u32_as_h2(u0.x));
        float2 b0 = __half22float2(u32_as_h2(u0.y));
        acc.x += a0.x; acc.y += a0.y; acc.z += b0.x; acc.w += b0.y;
    }
    uint2 o;
    o.x = h2_as_u32(__floats2half2_rn(acc.x, acc.y));
    o.y = h2_as_u32(__floats2half2_rn(acc.z, acc.w));
    g_a16[(size_t)w * 32 + lane] = o;
}

// --- Layer-2 aggregate (fp16 gather) + fused scale/bias/relu ----------------
__global__ __launch_bounds__(256) void agg2_kernel(const float* __restrict__ bias,
                                                   float* __restrict__ OUT) {
    int w = (blockIdx.x * blockDim.x + threadIdx.x) >> 5;
    if (w >= N2c) return;
    int lane = threadIdx.x & 31;
    int i = g_off2[w], end = g_off2[w + 1];
    float4 acc = make_float4(0.f, 0.f, 0.f, 0.f);
    const uint2* Y2 = (const uint2*)g_y16;
    for (; i + 1 < end; i += 2) {
        int s0 = g_csr2[i], s1 = g_csr2[i + 1];
        uint2 u0 = Y2[(size_t)s0 * 32 + lane];
        uint2 u1 = Y2[(size_t)s1 * 32 + lane];
        float2 a0 = __half22float2(u32_as_h2(u0.x));
        float2 b0 = __half22float2(u32_as_h2(u0.y));
        float2 a1 = __half22float2(u32_as_h2(u1.x));
        float2 b1 = __half22float2(u32_as_h2(u1.y));
        acc.x += a0.x + a1.x; acc.y += a0.y + a1.y;
        acc.z += b0.x + b1.x; acc.w += b0.y + b1.y;
    }
    if (i < end) {
        int s0 = g_csr2[i];
        uint2 u0 = Y2[(size_t)s0 * 32 + lane];
        float2 a0 = __half22float2(u32_as_h2(u0.x));
        float2 b0 = __half22float2(u32_as_h2(u0.y));
        acc.x += a0.x; acc.y += a0.y; acc.z += b0.x; acc.w += b0.y;
    }
    float s = g_deg[OFF_IN2 + w];
    float4 b = ((const float4*)bias)[lane];
    acc.x = fmaxf(fmaf(acc.x, s, b.x), 0.f);
    acc.y = fmaxf(fmaf(acc.y, s, b.y), 0.f);
    acc.z = fmaxf(fmaf(acc.z, s, b.z), 0.f);
    acc.w = fmaxf(fmaf(acc.w, s, b.w), 0.f);
    ((float4*)OUT)[(size_t)w * 32 + lane] = acc;
}

// ---------------------------------------------------------------------------
// Fused fp16 MLP (mma.m16n8k16.f16, fp32 accum). Per 128-row CTA:
//   Stage A (x2 n-passes): Hs[128][256] fp16 = relu(rs1*agg1@W1 + b1)  in SMEM
//   Stage B: y[128][128] fp16 = rs2 * Hs@W2, A-fragments from SMEM.
// All smem tiles stored k-contiguous as uint32 (=half2) rows.
// ---------------------------------------------------------------------------
#define TS 20                 // A/B tile row stride in uint32 (16 data + 4 pad)
#define HS2 132               // Hs row stride in uint32 (128 data + 4 pad)
#define AS_E (128 * TS)
#define BS_E (128 * TS)
#define HS_E (128 * HS2)
#define SMEM_FUSED ((HS_E + 2 * AS_E + 2 * BS_E) * 4)

__device__ __forceinline__ uint32_t smem_u32(const void* p) {
    return (uint32_t)__cvta_generic_to_shared(p);
}
__device__ __forceinline__ void cp16(uint32_t dst, const void* src, int src_bytes) {
    asm volatile("cp.async.cg.shared.global [%0], [%1], 16, %2;"
                 :: "r"(dst), "l"(src), "r"(src_bytes));
}
__device__ __forceinline__ void mma_f16(float c[4], const uint32_t a[4], const uint32_t b[2]) {
    asm volatile(
        "mma.sync.aligned.m16n8k16.row.col.f32.f16.f16.f32 "
        "{%0,%1,%2,%3}, {%4,%5,%6,%7}, {%8,%9}, {%0,%1,%2,%3};"
        : "+f"(c[0]), "+f"(c[1]), "+f"(c[2]), "+f"(c[3])
        : "r"(a[0]), "r"(a[1]), "r"(a[2]), "r"(a[3]), "r"(b[0]), "r"(b[1]));
}

__global__ __launch_bounds__(256) void fused_gemm(
    const __half* __restrict__ A16,   // agg1 [M,128] fp16
    __half* __restrict__ Y,           // [M,128] fp16
    const float* __restrict__ rs1, const float* __restrict__ b1,
    const float* __restrict__ rs2, int M)
{
    extern __shared__ uint32_t sm[];
    uint32_t (*Hs)[HS2]      = (uint32_t (*)[HS2])sm;
    uint32_t (*Ast)[128][TS] = (uint32_t (*)[128][TS])(sm + HS_E);
    uint32_t (*Bst)[128][TS] = (uint32_t (*)[128][TS])(sm + HS_E + 2 * AS_E);

    int tid = threadIdx.x;
    int wid = tid >> 5, lane = tid & 31;
    int g = lane >> 2, tig = lane & 3;
    int warp_m = (wid & 3) * 32;
    int warp_n = (wid >> 2) * 64;
    int rowBase = blockIdx.x * 128;

    // A-tile: 128 rows x 32 halfs (64B/row) from agg1; k-window = t*32
    auto loadA = [&](int t, int buf) {
#pragma unroll
        for (int i = 0; i < 2; i++) {
            int gI = tid + 256 * i;             // 512 granules of 16B
            int arow = gI >> 2, a16 = gI & 3;
            int gr = rowBase + arow;
            cp16(smem_u32(&Ast[buf][arow][a16 * 4]),
                 A16 + ((size_t)(gr < M ? gr : 0) * FIN + t * 32 + a16 * 8),
                 gr < M ? 16 : 0);
        }
    };
    // B-tile: 128 n-rows x 32 k-halfs from transposed fp16 weights (ldk = K of W)
    auto loadB = [&](const __half* Wt, int ldk, int nb, int t, int buf) {
#pragma unroll
        for (int i = 0; i < 2; i++) {
            int gI = tid + 256 * i;
            int brow = gI >> 2, b16 = gI & 3;
            cp16(smem_u32(&Bst[buf][brow][b16 * 4]),
                 Wt + ((size_t)(nb + brow) * ldk + t * 32 + b16 * 8), 16);
        }
    };

    // ---------------- Stage A: two 128x128 n-passes over W1 ----------------
#pragma unroll 1
    for (int pass = 0; pass < 2; pass++) {
        int cb = pass * 128;
        float c[2][8][4];
#pragma unroll
        for (int mi = 0; mi < 2; mi++)
#pragma unroll
            for (int ni = 0; ni < 8; ni++)
#pragma unroll
                for (int q = 0; q < 4; q++) c[mi][ni][q] = 0.f;

        loadA(0, 0);
        loadB(g_w1h, FIN, cb, 0, 0);
        asm volatile("cp.async.commit_group;" ::: "memory");

#pragma unroll 1
        for (int t = 0; t < 4; t++) {
            asm volatile("cp.async.wait_group 0;" ::: "memory");
            __syncthreads();
            if (t < 3) {
                loadA(t + 1, (t + 1) & 1);
                loadB(g_w1h, FIN, cb, t + 1, (t + 1) & 1);
                asm volatile("cp.async.commit_group;" ::: "memory");
            }
            int buf = t & 1;
#pragma unroll
            for (int kk2 = 0; kk2 < 16; kk2 += 8) {   // two k16 steps
                uint32_t af[2][4], bf[8][2];
#pragma unroll
                for (int mi = 0; mi < 2; mi++) {
                    int m = warp_m + mi * 16 + g;
                    af[mi][0] = Ast[buf][m][kk2 + tig];
                    af[mi][1] = Ast[buf][m + 8][kk2 + tig];
                    af[mi][2] = Ast[buf][m][kk2 + tig + 4];
                    af[mi][3] = Ast[buf][m + 8][kk2 + tig + 4];
                }
#pragma unroll
                for (int ni = 0; ni < 8; ni++) {
                    int n = warp_n + ni * 8 + g;
                    bf[ni][0] = Bst[buf][n][kk2 + tig];
                    bf[ni][1] = Bst[buf][n][kk2 + tig + 4];
                }
#pragma unroll
                for (int mi = 0; mi < 2; mi++)
#pragma unroll
                    for (int ni = 0; ni < 8; ni++)
                        mma_f16(c[mi][ni], af[mi], bf[ni]);
            }
        }

        // Epilogue -> Hs fp16 (scale, bias, relu)
#pragma unroll
        for (int mi = 0; mi < 2; mi++) {
#pragma unroll
            for (int half = 0; half < 2; half++) {
                int rl = warp_m + mi * 16 + g + half * 8;
                int row = rowBase + rl;
                float s = (row < M) ? rs1[row] : 0.f;
#pragma unroll
                for (int ni = 0; ni < 8; ni++) {
                    int col = cb + warp_n + ni * 8 + 2 * tig;
                    float v0 = 0.f, v1 = 0.f;
                    if (row < M) {
                        v0 = fmaxf(c[mi][ni][half * 2 + 0] * s + b1[col], 0.f);
                        v1 = fmaxf(c[mi][ni][half * 2 + 1] * s + b1[col + 1], 0.f);
                    }
                    Hs[rl][col >> 1] = h2_as_u32(__floats2half2_rn(v0, v1));
                }
            }
        }
    }

    // ---------------- Stage B: y = Hs @ W2 (K=256) -------------------------
    float c2[2][8][4];
#pragma unroll
    for (int mi = 0; mi < 2; mi++)
#pragma unroll
        for (int ni = 0; ni < 8; ni++)
#pragma unroll
            for (int q = 0; q < 4; q++) c2[mi][ni][q] = 0.f;

    loadB(g_w2h, FHID, 0, 0, 0);
    asm volatile("cp.async.commit_group;" ::: "memory");

#pragma unroll 1
    for (int t = 0; t < 8; t++) {
        asm volatile("cp.async.wait_group 0;" ::: "memory");
        __syncthreads();   // t=0: also publishes the Hs writes from stage A
        if (t < 7) {
            loadB(g_w2h, FHID, 0, t + 1, (t + 1) & 1);
            asm volatile("cp.async.commit_group;" ::: "memory");
        }
        int buf = t & 1;
#pragma unroll
        for (int kk2 = 0; kk2 < 16; kk2 += 8) {
            uint32_t af[2][4], bf[8][2];
            int kb2 = t * 16 + kk2;
#pragma unroll
            for (int mi = 0; mi < 2; mi++) {
                int m = warp_m + mi * 16 + g;
                af[mi][0] = Hs[m][kb2 + tig];
                af[mi][1] = Hs[m + 8][kb2 + tig];
                af[mi][2] = Hs[m][kb2 + tig + 4];
                af[mi][3] = Hs[m + 8][kb2 + tig + 4];
            }
#pragma unroll
            for (int ni = 0; ni < 8; ni++) {
                int n = warp_n + ni * 8 + g;
                bf[ni][0] = Bst[buf][n][kk2 + tig];
                bf[ni][1] = Bst[buf][n][kk2 + tig + 4];
            }
#pragma unroll
            for (int mi = 0; mi < 2; mi++)
#pragma unroll
                for (int ni = 0; ni < 8; ni++)
                    mma_f16(c2[mi][ni], af[mi], bf[ni]);
        }
    }

    // Epilogue -> Y (fp16, pre-scaled by outdeg2^-1/2)
#pragma unroll
    for (int mi = 0; mi < 2; mi++) {
#pragma unroll
        for (int half = 0; half < 2; half++) {
            int row = rowBase + warp_m + mi * 16 + g + half * 8;
            if (row >= M) continue;
            float s = rs2[row];
#pragma unroll
            for (int ni = 0; ni < 8; ni++) {
                int col = warp_n + ni * 8 + 2 * tig;
                __half2 h2 = __floats2half2_rn(c2[mi][ni][half * 2 + 0] * s,
                                               c2[mi][ni][half * 2 + 1] * s);
                *(__half2*)&Y[(size_t)row * FOUT + col] = h2;
            }
        }
    }
}

// ---------------------------------------------------------------------------
extern "C" void kernel_launch(void* const* d_in, const int* in_sizes, int n_in,
                              void* d_out, int out_size) {
    const float* x   = (const float*)d_in[0];
    const float* W1  = (const float*)d_in[1];
    const float* b1  = (const float*)d_in[2];
    const float* W2  = (const float*)d_in[3];
    const float* b2  = (const float*)d_in[4];
    const int* src1  = (const int*)d_in[5];
    const int* dst1  = (const int*)d_in[6];
    const int* src2  = (const int*)d_in[7];
    const int* dst2  = (const int*)d_in[8];
    float* out = (float*)d_out;

    float* deg;
    __half *a16, *y16;
    cudaGetSymbolAddress((void**)&deg, g_deg);
    cudaGetSymbolAddress((void**)&a16, g_a16);
    cudaGetSymbolAddress((void**)&y16, g_y16);

    cudaFuncSetAttribute(fused_gemm, cudaFuncAttributeMaxDynamicSharedMemorySize, SMEM_FUSED);

    const int TB = 256;

    // prep must cover BOTH the icnt zeroing (DEG_TOT/4) and weight transpose
    int prep_threads = (DEG_TOT / 4 > FIN * FHID) ? DEG_TOT / 4 : FIN * FHID;
    prep_kernel<<<(prep_threads + TB - 1) / TB, TB>>>(W1, W2);
    degree_kernel<<<(E1c + TB - 1) / TB, TB>>>(src1, dst1, src2, dst2);
    convert_deg_kernel<<<(DEG_TOT + TB - 1) / TB, TB>>>();
    convert_x_kernel<<<(N0c * 32 + TB - 1) / TB, TB>>>(x);
    scan_pass1<<<NBT, 256>>>();
    scan_pass2<<<1, 512>>>();
    scan_pass3<<<NBT, 256>>>();
    fill_kernel<<<(E1c + TB - 1) / TB, TB>>>(src1, dst1, src2, dst2);

    // Layer 1 aggregate (fp16 gather): a16 = fp16( segsum(xh) )
    agg1_kernel<<<(N1c * 32 + TB - 1) / TB, TB>>>();

    // Fused: h = fp16(relu(rs1*a16@W1+b1)) [smem]; y16 = fp16(rs2*(h@W2))
    fused_gemm<<<(N1c + 127) / 128, 256, SMEM_FUSED>>>(
        a16, y16, deg + OFF_IN1, b1, deg + OFF_OUT2, N1c);

    // Layer 2 aggregate + fused scale/bias/relu -> out
    agg2_kernel<<<(N2c * 32 + TB - 1) / TB, TB>>>(b2, out);
}